// round 5
// baseline (speedup 1.0000x reference)
#include <cuda_runtime.h>
#include <cstdint>

#define BROWS 64
#define L 16384
#define NT 1024
#define NW 32
#define CHUNK 16
#define NIMF 6
#define MAXIT 12
// pad 4 floats per 16 -> per-thread chunk stride = 20 words (80B): float4 phases conflict-free
#define LP2 (L + (L >> 2))
#define PH(i) ((i) + (((i) >> 4) << 2))

// -------- device-global scratch (allocation-free contract) --------
__device__ float    g_res[BROWS * L];
__device__ double   g_part[2][BROWS][4];
__device__ unsigned g_count = 0;

__device__ __forceinline__ float negInf() { return __int_as_float(0xff800000); }
__device__ __forceinline__ float posInf() { return __int_as_float(0x7f800000); }

// -------- grid barrier: all 64 CTAs co-resident (1 wave), monotonic counter --------
__device__ __forceinline__ void gbar(unsigned* s_gen) {
    __syncthreads();
    if (threadIdx.x == 0) {
        unsigned g = ++(*s_gen);
        __threadfence();
        atomicAdd(&g_count, 1u);
        volatile unsigned* vc = &g_count;
        while (*vc < (unsigned)BROWS * g) { __nanosleep(20); }
        __threadfence();
    }
    __syncthreads();
}

// -------- fused block collectives: packed suffix-min, packed prefix-max, packed sum --------
// ubuf: >= 3*NW unsigned. Returns exclusive suffix-min (offn), exclusive prefix-max (offl), total (tot).
__device__ __forceinline__ void fused_coll(unsigned vmin, unsigned vmax, unsigned vsum,
                                           unsigned* ubuf,
                                           unsigned& offn, unsigned& offl, unsigned& tot) {
    const int lane = threadIdx.x & 31, wid = threadIdx.x >> 5;
    unsigned imin = vmin, imax = vmax, s = vsum;
#pragma unroll
    for (int d = 1; d < 32; d <<= 1) {
        unsigned a = __shfl_down_sync(0xffffffffu, imin, d);
        if (lane + d < 32) imin = __vminu2(imin, a);
        unsigned b = __shfl_up_sync(0xffffffffu, imax, d);
        if (lane >= d) imax = __vmaxs2(imax, b);
        s += __shfl_xor_sync(0xffffffffu, s, d);
    }
    if (lane == 0)  { ubuf[wid] = imin; ubuf[2 * NW + wid] = s; }
    if (lane == 31) { ubuf[NW + wid] = imax; }
    __syncthreads();
    if (wid == 0) {
        unsigned wm = ubuf[lane];
        unsigned wx = ubuf[NW + lane];
        unsigned ws = ubuf[2 * NW + lane];
#pragma unroll
        for (int d = 1; d < 32; d <<= 1) {
            unsigned a = __shfl_down_sync(0xffffffffu, wm, d);
            if (lane + d < 32) wm = __vminu2(wm, a);
            unsigned b = __shfl_up_sync(0xffffffffu, wx, d);
            if (lane >= d) wx = __vmaxs2(wx, b);
            ws += __shfl_xor_sync(0xffffffffu, ws, d);
        }
        ubuf[lane] = wm;
        ubuf[NW + lane] = wx;
        if (lane == 0) ubuf[2 * NW] = ws;
    }
    __syncthreads();
    unsigned woffn = (wid < NW - 1) ? ubuf[wid + 1] : 0x40004000u;   // (L, L)
    unsigned lexn  = __shfl_down_sync(0xffffffffu, imin, 1);
    offn = (lane < 31) ? __vminu2(woffn, lexn) : woffn;
    unsigned woffl = (wid > 0) ? ubuf[NW + wid - 1] : 0xffffffffu;   // (-1, -1)
    unsigned lexl  = __shfl_up_sync(0xffffffffu, imax, 1);
    offl = (lane > 0) ? __vmaxs2(woffl, lexl) : woffl;
    tot = ubuf[2 * NW];
    __syncthreads();
}

// -------- float exclusive prefix-max / prefix-min (rare fallback path) --------
__device__ __forceinline__ float pmax_f_excl(float v, float* wbuf) {
    const int lane = threadIdx.x & 31, wid = threadIdx.x >> 5;
    float incl = v;
#pragma unroll
    for (int d = 1; d < 32; d <<= 1) {
        float u = __shfl_up_sync(0xffffffffu, incl, d);
        if (lane >= d) incl = fmaxf(incl, u);
    }
    if (lane == 31) wbuf[wid] = incl;
    __syncthreads();
    if (wid == 0) {
        float w = wbuf[lane];
#pragma unroll
        for (int d = 1; d < 32; d <<= 1) {
            float u = __shfl_up_sync(0xffffffffu, w, d);
            if (lane >= d) w = fmaxf(w, u);
        }
        wbuf[lane] = w;
    }
    __syncthreads();
    float woff = (wid > 0) ? wbuf[wid - 1] : negInf();
    float lex  = __shfl_up_sync(0xffffffffu, incl, 1);
    float ex   = (lane > 0) ? fmaxf(woff, lex) : woff;
    __syncthreads();
    return ex;
}

__device__ __forceinline__ float pmin_f_excl(float v, float* wbuf) {
    const int lane = threadIdx.x & 31, wid = threadIdx.x >> 5;
    float incl = v;
#pragma unroll
    for (int d = 1; d < 32; d <<= 1) {
        float u = __shfl_up_sync(0xffffffffu, incl, d);
        if (lane >= d) incl = fminf(incl, u);
    }
    if (lane == 31) wbuf[wid] = incl;
    __syncthreads();
    if (wid == 0) {
        float w = wbuf[lane];
#pragma unroll
        for (int d = 1; d < 32; d <<= 1) {
            float u = __shfl_up_sync(0xffffffffu, w, d);
            if (lane >= d) w = fminf(w, u);
        }
        wbuf[lane] = w;
    }
    __syncthreads();
    float woff = (wid > 0) ? wbuf[wid - 1] : posInf();
    float lex  = __shfl_up_sync(0xffffffffu, incl, 1);
    float ex   = (lane > 0) ? fminf(woff, lex) : woff;
    __syncthreads();
    return ex;
}

// -------- two doubles reduced together --------
__device__ __forceinline__ void block_sum_d2(double& a, double& b, double* wbuf) {
#pragma unroll
    for (int d = 16; d; d >>= 1) {
        a += __shfl_down_sync(0xffffffffu, a, d);
        b += __shfl_down_sync(0xffffffffu, b, d);
    }
    const int lane = threadIdx.x & 31, wid = threadIdx.x >> 5;
    if (lane == 0) { wbuf[wid] = a; wbuf[NW + wid] = b; }
    __syncthreads();
    if (wid == 0) {
        double wa = wbuf[lane], wb = wbuf[NW + lane];
#pragma unroll
        for (int d = 16; d; d >>= 1) {
            wa += __shfl_down_sync(0xffffffffu, wa, d);
            wb += __shfl_down_sync(0xffffffffu, wb, d);
        }
        if (lane == 0) { wbuf[0] = wa; wbuf[NW] = wb; }
    }
    __syncthreads();
    a = wbuf[0]; b = wbuf[NW];
    __syncthreads();
}

// -------- one fused sifting pass (R3-exact numerics, R4 structure) --------
__device__ void sift_pass(const float* __restrict__ hc, float* __restrict__ ho,
                          unsigned* ubuf, float* fbuf,
                          double& o_sm, double& o_sh2)
{
    const int t  = threadIdx.x;
    const int lo = t * CHUNK;
    const float* cbase = hc + PH(lo);

    // ---- walk A: build peak-position bitmasks for both envelopes ----
    float h16[CHUNK];
#pragma unroll
    for (int q = 0; q < 4; ++q)
        *(float4*)&h16[4 * q] = ((const float4*)cbase)[q];
    float prev  = (t > 0)      ? hc[PH(lo - 1)]     : 0.f;
    float nextB = (t < NT - 1) ? hc[PH(lo + CHUNK)] : 0.f;

    unsigned mU = 0, mL = 0;
#pragma unroll
    for (int j = 0; j < CHUNK; ++j) {
        float cur = h16[j];
        float nxt = (j < CHUNK - 1) ? h16[j + 1] : nextB;
        mU |= (unsigned)((prev < cur) & (cur > nxt)) << j;
        mL |= (unsigned)((prev > cur) & (cur < nxt)) << j;
        prev = cur;
    }
    if (t == 0)      { mU &= ~1u;     mL &= ~1u;     }
    if (t == NT - 1) { mU &= 0x7fffu; mL &= 0x7fffu; }

    int run_u = mU ? lo + (__ffs(mU) - 1) : L;
    int run_l = mL ? lo + (__ffs(mL) - 1) : L;
    int cm_u  = mU ? lo + (31 - __clz((int)mU)) : -1;
    int cm_l  = mL ? lo + (31 - __clz((int)mL)) : -1;
    unsigned cnt = (unsigned)__popc(mU) | ((unsigned)__popc(mL) << 16);

    unsigned offn, offl, tot;
    fused_coll((unsigned)run_u | ((unsigned)run_l << 16),
               ((unsigned)cm_u & 0xffffu) | (((unsigned)cm_l & 0xffffu) << 16),
               cnt, ubuf, offn, offl, tot);

    const int  off_nu = (int)(offn & 0xffffu);
    const int  off_nl = (int)(offn >> 16);
    const int  off_lu = (int)(short)(offl & 0xffffu);
    const int  off_ll = (int)(short)(offl >> 16);
    const bool few_u  = (tot & 0xffffu) < 2u;   // block-uniform
    const bool few_l  = (tot >> 16)     < 2u;   // block-uniform

    float fbU = negInf(), fbL = posInf();
    if (few_u) {
        float cm = negInf();
#pragma unroll
        for (int j = 0; j < CHUNK; ++j) cm = fmaxf(cm, h16[j]);
        fbU = pmax_f_excl(cm, fbuf);
    }
    if (few_l) {
        float cm = posInf();
#pragma unroll
        for (int j = 0; j < CHUNK; ++j) cm = fminf(cm, h16[j]);
        fbL = pmin_f_excl(cm, fbuf);
    }

    // ---- walk B: per-element exact interpolation (bitwise-matching reference) ----
    int   runl_u = off_lu, runl_l = off_ll;
    float vl_u = hc[PH(max(runl_u, 0))];
    float vl_l = hc[PH(max(runl_l, 0))];
    int   cur_nu = -0x40000000, cur_nl = -0x40000000;
    float vr_u = 0.f, vr_l = 0.f;
    double sm = 0.0, sh2 = 0.0;
    float* obase = ho + PH(lo);

#pragma unroll
    for (int q = 0; q < 4; ++q) {
        float4 ov;
#pragma unroll
        for (int r = 0; r < 4; ++r) {
            const int j = 4 * q + r;
            const int i = lo + j;
            const float hv = h16[j];

            if ((mU >> j) & 1u) { runl_u = i; vl_u = hv; }
            unsigned remU = mU >> j;
            int nu = remU ? i + (__ffs(remU) - 1) : off_nu;
            if (nu != cur_nu) { cur_nu = nu; vr_u = hc[PH(min(nu, L - 1))]; }
            float eu;
            {
                int den = nu - runl_u;
                eu = (den > 0) ? vl_u + ((float)(i - runl_u) / (float)den) * (vr_u - vl_u)
                               : vl_u;
                if (runl_u < 0) eu = vr_u;   // left of first peak
                if (nu >= L)    eu = vl_u;   // right of last peak
            }
            if (few_u) { fbU = fmaxf(fbU, hv); eu = fbU; }

            if ((mL >> j) & 1u) { runl_l = i; vl_l = hv; }
            unsigned remL = mL >> j;
            int nl = remL ? i + (__ffs(remL) - 1) : off_nl;
            if (nl != cur_nl) { cur_nl = nl; vr_l = hc[PH(min(nl, L - 1))]; }
            float el;
            {
                int den = nl - runl_l;
                el = (den > 0) ? vl_l + ((float)(i - runl_l) / (float)den) * (vr_l - vl_l)
                               : vl_l;
                if (runl_l < 0) el = vr_l;
                if (nl >= L)    el = vl_l;
            }
            if (few_l) { fbL = fminf(fbL, hv); el = fbL; }

            float mean = 0.5f * (eu + el);
            float o = hv - mean;
            sm  += (double)mean * (double)mean;
            sh2 += (double)hv * (double)hv;
            switch (r) {
                case 0: ov.x = o; break;
                case 1: ov.y = o; break;
                case 2: ov.z = o; break;
                default: ov.w = o; break;
            }
        }
        ((float4*)obase)[q] = ov;
    }
    o_sm  = sm;
    o_sh2 = sh2;
}

__global__ void __launch_bounds__(NT, 1)
emd_kernel(const float* __restrict__ x, float* __restrict__ out)
{
    extern __shared__ unsigned char dynsm[];
    float* bufA = (float*)dynsm;      // LP2 floats
    float* bufB = bufA + LP2;         // LP2 floats

    __shared__ unsigned s_u[3 * NW];
    __shared__ float    s_f[NW + 1];
    __shared__ double   s_d[2 * NW];
    __shared__ unsigned s_gen;
    __shared__ int      s_flag;

    const int t   = threadIdx.x;
    const int lo  = t * CHUNK;
    const int row = blockIdx.x;
    if (t == 0) s_gen = 0u;

    const float* xr   = x + (size_t)row * L;
    float*       resr = g_res + (size_t)row * L;

    // res = x (re-initialized every launch: deterministic)
#pragma unroll
    for (int q = 0; q < 4; ++q)
        *(float4*)(resr + lo + 4 * q) = *(const float4*)(xr + lo + 4 * q);

    int  phase      = 0;
    bool outer_done = false;

    for (int im = 0; im < NIMF; ++im) {
        float* outim = out + ((size_t)im * BROWS + row) * L;
        if (outer_done) {
            float4 z = make_float4(0.f, 0.f, 0.f, 0.f);
#pragma unroll
            for (int q = 0; q < 4; ++q) *(float4*)(outim + lo + 4 * q) = z;
            continue;  // globally uniform -> barrier counts stay consistent
        }

        float* hc = bufA;
        float* ho = bufB;
#pragma unroll
        for (int q = 0; q < 4; ++q)
            ((float4*)(hc + PH(lo)))[q] = *(const float4*)(resr + lo + 4 * q);
        __syncthreads();

        // ---- sifting (double-buffered) ----
        for (int it = 0; it < MAXIT; ++it) {
            double sm, sh2;
            sift_pass(hc, ho, s_u, s_f, sm, sh2);
            block_sum_d2(sm, sh2, s_d);
            if (t == 0) {
                g_part[phase & 1][row][0] = sm;
                g_part[phase & 1][row][1] = sh2;
            }
            gbar(&s_gen);
            // parallel flag reduction over 64 rows
            if (t < 64) {
                double a = g_part[phase & 1][t][0];
                double b = g_part[phase & 1][t][1];
#pragma unroll
                for (int d = 16; d; d >>= 1) {
                    a += __shfl_down_sync(0xffffffffu, a, d);
                    b += __shfl_down_sync(0xffffffffu, b, d);
                }
                if ((t & 31) == 0) { s_d[t >> 5] = a; s_d[2 + (t >> 5)] = b; }
            }
            __syncthreads();
            if (t == 0) {
                double A = s_d[0] + s_d[1], Bs = s_d[2] + s_d[3];
                s_flag = (A / (Bs + 1e-8) < 0.05) ? 1 : 0;
            }
            phase++;
            __syncthreads();
            if (s_flag) break;            // converged: keep hc (pre-subtract), matching reference
            float* tmp = hc; hc = ho; ho = tmp;   // accept h - mean
        }

        // ---- emit IMF, update residual, global flatness check ----
        float ar = 0.f, ar2 = 0.f;
#pragma unroll
        for (int q = 0; q < 4; ++q) {
            float4 hv = ((const float4*)(hc + PH(lo)))[q];
            float4 rr = *(const float4*)(resr + lo + 4 * q);
            float4 nr;
            nr.x = rr.x - hv.x; nr.y = rr.y - hv.y;
            nr.z = rr.z - hv.z; nr.w = rr.w - hv.w;
            *(float4*)(outim + lo + 4 * q) = hv;
            *(float4*)(resr + lo + 4 * q)  = nr;
            ((float4*)(ho + PH(lo)))[q]    = nr;
            ar  += nr.x + nr.y + nr.z + nr.w;
            ar2 += nr.x * nr.x + nr.y * nr.y + nr.z * nr.z + nr.w * nr.w;
        }
        __syncthreads();
        float ad = 0.f, ad2 = 0.f;
        {
            float c16[CHUNK];
#pragma unroll
            for (int q = 0; q < 4; ++q)
                *(float4*)&c16[4 * q] = ((const float4*)(ho + PH(lo)))[q];
            float nb = (t < NT - 1) ? ho[PH(lo + CHUNK)] : 0.f;
#pragma unroll
            for (int j = 0; j < CHUNK; ++j) {
                float nx = (j < CHUNK - 1) ? c16[j + 1] : nb;
                if (lo + j < L - 1) {
                    float d = nx - c16[j];
                    ad  += d;
                    ad2 += d * d;
                }
            }
        }
        double Sd = (double)ad, Sd2 = (double)ad2;
        double Sr = (double)ar, Sr2 = (double)ar2;
        block_sum_d2(Sd, Sd2, s_d);
        block_sum_d2(Sr, Sr2, s_d);
        if (t == 0) {
            double* p = &g_part[phase & 1][row][0];
            p[0] = Sd; p[1] = Sd2; p[2] = Sr; p[3] = Sr2;
        }
        gbar(&s_gen);
        if (t < 64) {
            const double* p = &g_part[phase & 1][t][0];
            double a = p[0], b = p[1], c = p[2], e = p[3];
#pragma unroll
            for (int d = 16; d; d >>= 1) {
                a += __shfl_down_sync(0xffffffffu, a, d);
                b += __shfl_down_sync(0xffffffffu, b, d);
                c += __shfl_down_sync(0xffffffffu, c, d);
                e += __shfl_down_sync(0xffffffffu, e, d);
            }
            if ((t & 31) == 0) {
                int w = t >> 5;
                s_d[4 * w + 0] = a; s_d[4 * w + 1] = b;
                s_d[4 * w + 2] = c; s_d[4 * w + 3] = e;
            }
        }
        __syncthreads();
        if (t == 0) {
            double a = s_d[0] + s_d[4], b = s_d[1] + s_d[5];
            double c = s_d[2] + s_d[6], e = s_d[3] + s_d[7];
            double ndv = (double)BROWS * (double)(L - 1);
            double nrv = (double)BROWS * (double)L;
            double vard = (b - a * a / ndv) / (ndv - 1.0);
            double varr = (e - c * c / nrv) / (nrv - 1.0);
            s_flag = (vard < 0.05 * varr) ? 1 : 0;
        }
        phase++;
        __syncthreads();
        if (s_flag) outer_done = true;
    }

    // final residual
    float* outres = out + ((size_t)NIMF * BROWS + row) * L;
#pragma unroll
    for (int q = 0; q < 4; ++q)
        *(float4*)(outres + lo + 4 * q) = *(const float4*)(resr + lo + 4 * q);

    // reset barrier counter for the next (graph-replayed) launch
    gbar(&s_gen);
    if (row == 0 && t == 0) g_count = 0u;
}

extern "C" void kernel_launch(void* const* d_in, const int* in_sizes, int n_in,
                              void* d_out, int out_size) {
    (void)in_sizes; (void)n_in; (void)out_size;
    const size_t shmem = (size_t)(2 * LP2) * sizeof(float);
    cudaFuncSetAttribute(emd_kernel, cudaFuncAttributeMaxDynamicSharedMemorySize, (int)shmem);
    emd_kernel<<<BROWS, NT, shmem>>>((const float*)d_in[0], (float*)d_out);
}

// round 6
// speedup vs baseline: 1.1505x; 1.1505x over previous
#include <cuda_runtime.h>
#include <cstdint>

#define BROWS 64
#define L 16384
#define NT 1024
#define NW 32
#define CHUNK 16
#define NIMF 6
#define MAXIT 12
// pad 4 floats per 16 -> per-thread chunk stride = 20 words (80B): float4 phases conflict-free
#define LP2 (L + (L >> 2))
#define PH(i) ((i) + (((i) >> 4) << 2))

// -------- device-global scratch (allocation-free contract) --------
__device__ float    g_res[BROWS * L];
__device__ double   g_part[2][BROWS][4];
__device__ unsigned g_seq[BROWS];        // per-row phase tags (reset to 0 at kernel end)
__device__ unsigned g_count = 0;         // end-of-kernel rendezvous only

__device__ __forceinline__ float negInf() { return __int_as_float(0xff800000); }
__device__ __forceinline__ float posInf() { return __int_as_float(0x7f800000); }

// -------- fused block collectives: packed suffix-min, packed prefix-max, packed sum --------
__device__ __forceinline__ void fused_coll(unsigned vmin, unsigned vmax, unsigned vsum,
                                           unsigned* ubuf,
                                           unsigned& offn, unsigned& offl, unsigned& tot) {
    const int lane = threadIdx.x & 31, wid = threadIdx.x >> 5;
    unsigned imin = vmin, imax = vmax, s = vsum;
#pragma unroll
    for (int d = 1; d < 32; d <<= 1) {
        unsigned a = __shfl_down_sync(0xffffffffu, imin, d);
        if (lane + d < 32) imin = __vminu2(imin, a);
        unsigned b = __shfl_up_sync(0xffffffffu, imax, d);
        if (lane >= d) imax = __vmaxs2(imax, b);
        s += __shfl_xor_sync(0xffffffffu, s, d);
    }
    if (lane == 0)  { ubuf[wid] = imin; ubuf[2 * NW + wid] = s; }
    if (lane == 31) { ubuf[NW + wid] = imax; }
    __syncthreads();
    if (wid == 0) {
        unsigned wm = ubuf[lane];
        unsigned wx = ubuf[NW + lane];
        unsigned ws = ubuf[2 * NW + lane];
#pragma unroll
        for (int d = 1; d < 32; d <<= 1) {
            unsigned a = __shfl_down_sync(0xffffffffu, wm, d);
            if (lane + d < 32) wm = __vminu2(wm, a);
            unsigned b = __shfl_up_sync(0xffffffffu, wx, d);
            if (lane >= d) wx = __vmaxs2(wx, b);
            ws += __shfl_xor_sync(0xffffffffu, ws, d);
        }
        ubuf[lane] = wm;
        ubuf[NW + lane] = wx;
        if (lane == 0) ubuf[2 * NW] = ws;
    }
    __syncthreads();
    unsigned woffn = (wid < NW - 1) ? ubuf[wid + 1] : 0x40004000u;   // (L, L)
    unsigned lexn  = __shfl_down_sync(0xffffffffu, imin, 1);
    offn = (lane < 31) ? __vminu2(woffn, lexn) : woffn;
    unsigned woffl = (wid > 0) ? ubuf[NW + wid - 1] : 0xffffffffu;   // (-1, -1)
    unsigned lexl  = __shfl_up_sync(0xffffffffu, imax, 1);
    offl = (lane > 0) ? __vmaxs2(woffl, lexl) : woffl;
    tot = ubuf[2 * NW];
    __syncthreads();
}

// -------- float exclusive prefix-max / prefix-min (rare fallback path) --------
__device__ __forceinline__ float pmax_f_excl(float v, float* wbuf) {
    const int lane = threadIdx.x & 31, wid = threadIdx.x >> 5;
    float incl = v;
#pragma unroll
    for (int d = 1; d < 32; d <<= 1) {
        float u = __shfl_up_sync(0xffffffffu, incl, d);
        if (lane >= d) incl = fmaxf(incl, u);
    }
    if (lane == 31) wbuf[wid] = incl;
    __syncthreads();
    if (wid == 0) {
        float w = wbuf[lane];
#pragma unroll
        for (int d = 1; d < 32; d <<= 1) {
            float u = __shfl_up_sync(0xffffffffu, w, d);
            if (lane >= d) w = fmaxf(w, u);
        }
        wbuf[lane] = w;
    }
    __syncthreads();
    float woff = (wid > 0) ? wbuf[wid - 1] : negInf();
    float lex  = __shfl_up_sync(0xffffffffu, incl, 1);
    float ex   = (lane > 0) ? fmaxf(woff, lex) : woff;
    __syncthreads();
    return ex;
}

__device__ __forceinline__ float pmin_f_excl(float v, float* wbuf) {
    const int lane = threadIdx.x & 31, wid = threadIdx.x >> 5;
    float incl = v;
#pragma unroll
    for (int d = 1; d < 32; d <<= 1) {
        float u = __shfl_up_sync(0xffffffffu, incl, d);
        if (lane >= d) incl = fminf(incl, u);
    }
    if (lane == 31) wbuf[wid] = incl;
    __syncthreads();
    if (wid == 0) {
        float w = wbuf[lane];
#pragma unroll
        for (int d = 1; d < 32; d <<= 1) {
            float u = __shfl_up_sync(0xffffffffu, w, d);
            if (lane >= d) w = fminf(w, u);
        }
        wbuf[lane] = w;
    }
    __syncthreads();
    float woff = (wid > 0) ? wbuf[wid - 1] : posInf();
    float lex  = __shfl_up_sync(0xffffffffu, incl, 1);
    float ex   = (lane > 0) ? fminf(woff, lex) : woff;
    __syncthreads();
    return ex;
}

// -------- block sums: totals valid on thread 0 only (no broadcast syncs) --------
__device__ __forceinline__ void block_sum2_to0(double& a, double& b, double* wbuf) {
#pragma unroll
    for (int d = 16; d; d >>= 1) {
        a += __shfl_down_sync(0xffffffffu, a, d);
        b += __shfl_down_sync(0xffffffffu, b, d);
    }
    const int lane = threadIdx.x & 31, wid = threadIdx.x >> 5;
    if (lane == 0) { wbuf[wid] = a; wbuf[NW + wid] = b; }
    __syncthreads();
    if (wid == 0) {
        double wa = wbuf[lane], wb = wbuf[NW + lane];
#pragma unroll
        for (int d = 16; d; d >>= 1) {
            wa += __shfl_down_sync(0xffffffffu, wa, d);
            wb += __shfl_down_sync(0xffffffffu, wb, d);
        }
        a = wa; b = wb;   // meaningful on lane 0 (== t0)
    }
}

__device__ __forceinline__ void block_sum4_to0(double& a, double& b, double& c, double& e,
                                               double* wbuf) {
#pragma unroll
    for (int d = 16; d; d >>= 1) {
        a += __shfl_down_sync(0xffffffffu, a, d);
        b += __shfl_down_sync(0xffffffffu, b, d);
        c += __shfl_down_sync(0xffffffffu, c, d);
        e += __shfl_down_sync(0xffffffffu, e, d);
    }
    const int lane = threadIdx.x & 31, wid = threadIdx.x >> 5;
    if (lane == 0) {
        wbuf[wid] = a; wbuf[NW + wid] = b;
        wbuf[2 * NW + wid] = c; wbuf[3 * NW + wid] = e;
    }
    __syncthreads();
    if (wid == 0) {
        double wa = wbuf[lane], wb = wbuf[NW + lane];
        double wc = wbuf[2 * NW + lane], we = wbuf[3 * NW + lane];
#pragma unroll
        for (int d = 16; d; d >>= 1) {
            wa += __shfl_down_sync(0xffffffffu, wa, d);
            wb += __shfl_down_sync(0xffffffffu, wb, d);
            wc += __shfl_down_sync(0xffffffffu, wc, d);
            we += __shfl_down_sync(0xffffffffu, we, d);
        }
        a = wa; b = wb; c = wc; e = we;   // meaningful on lane 0 (== t0)
    }
}

// -------- one fused sifting pass (R3-exact numerics: exact div + fp32 sd partials) --------
__device__ void sift_pass(const float* __restrict__ hc, float* __restrict__ ho,
                          unsigned* ubuf, float* fbuf,
                          float& o_m, float& o_h2)
{
    const int t  = threadIdx.x;
    const int lo = t * CHUNK;
    const float* cbase = hc + PH(lo);

    // ---- walk A: build peak-position bitmasks for both envelopes ----
    float h16[CHUNK];
#pragma unroll
    for (int q = 0; q < 4; ++q)
        *(float4*)&h16[4 * q] = ((const float4*)cbase)[q];
    float prev  = (t > 0)      ? hc[PH(lo - 1)]     : 0.f;
    float nextB = (t < NT - 1) ? hc[PH(lo + CHUNK)] : 0.f;

    unsigned mU = 0, mL = 0;
#pragma unroll
    for (int j = 0; j < CHUNK; ++j) {
        float cur = h16[j];
        float nxt = (j < CHUNK - 1) ? h16[j + 1] : nextB;
        mU |= (unsigned)((prev < cur) & (cur > nxt)) << j;
        mL |= (unsigned)((prev > cur) & (cur < nxt)) << j;
        prev = cur;
    }
    if (t == 0)      { mU &= ~1u;     mL &= ~1u;     }
    if (t == NT - 1) { mU &= 0x7fffu; mL &= 0x7fffu; }

    int run_u = mU ? lo + (__ffs(mU) - 1) : L;
    int run_l = mL ? lo + (__ffs(mL) - 1) : L;
    int cm_u  = mU ? lo + (31 - __clz((int)mU)) : -1;
    int cm_l  = mL ? lo + (31 - __clz((int)mL)) : -1;
    unsigned cnt = (unsigned)__popc(mU) | ((unsigned)__popc(mL) << 16);

    unsigned offn, offl, tot;
    fused_coll((unsigned)run_u | ((unsigned)run_l << 16),
               ((unsigned)cm_u & 0xffffu) | (((unsigned)cm_l & 0xffffu) << 16),
               cnt, ubuf, offn, offl, tot);

    const int  off_nu = (int)(offn & 0xffffu);
    const int  off_nl = (int)(offn >> 16);
    const int  off_lu = (int)(short)(offl & 0xffffu);
    const int  off_ll = (int)(short)(offl >> 16);
    const bool few_u  = (tot & 0xffffu) < 2u;   // block-uniform
    const bool few_l  = (tot >> 16)     < 2u;   // block-uniform

    float fbU = negInf(), fbL = posInf();
    if (few_u) {
        float cm = negInf();
#pragma unroll
        for (int j = 0; j < CHUNK; ++j) cm = fmaxf(cm, h16[j]);
        fbU = pmax_f_excl(cm, fbuf);
    }
    if (few_l) {
        float cm = posInf();
#pragma unroll
        for (int j = 0; j < CHUNK; ++j) cm = fminf(cm, h16[j]);
        fbL = pmin_f_excl(cm, fbuf);
    }

    // ---- walk B: per-element exact interpolation (bitwise-matching reference) ----
    int   runl_u = off_lu, runl_l = off_ll;
    float vl_u = hc[PH(max(runl_u, 0))];
    float vl_l = hc[PH(max(runl_l, 0))];
    int   cur_nu = -0x40000000, cur_nl = -0x40000000;
    float vr_u = 0.f, vr_l = 0.f;
    float acc_m = 0.f, acc_h = 0.f;
    float* obase = ho + PH(lo);

#pragma unroll
    for (int q = 0; q < 4; ++q) {
        float4 ov;
#pragma unroll
        for (int r = 0; r < 4; ++r) {
            const int j = 4 * q + r;
            const int i = lo + j;
            const float hv = h16[j];

            if ((mU >> j) & 1u) { runl_u = i; vl_u = hv; }
            unsigned remU = mU >> j;
            int nu = remU ? i + (__ffs(remU) - 1) : off_nu;
            if (nu != cur_nu) { cur_nu = nu; vr_u = hc[PH(min(nu, L - 1))]; }
            float eu;
            {
                int den = nu - runl_u;
                eu = (den > 0) ? vl_u + ((float)(i - runl_u) / (float)den) * (vr_u - vl_u)
                               : vl_u;
                if (runl_u < 0) eu = vr_u;   // left of first peak
                if (nu >= L)    eu = vl_u;   // right of last peak
            }
            if (few_u) { fbU = fmaxf(fbU, hv); eu = fbU; }

            if ((mL >> j) & 1u) { runl_l = i; vl_l = hv; }
            unsigned remL = mL >> j;
            int nl = remL ? i + (__ffs(remL) - 1) : off_nl;
            if (nl != cur_nl) { cur_nl = nl; vr_l = hc[PH(min(nl, L - 1))]; }
            float el;
            {
                int den = nl - runl_l;
                el = (den > 0) ? vl_l + ((float)(i - runl_l) / (float)den) * (vr_l - vl_l)
                               : vl_l;
                if (runl_l < 0) el = vr_l;
                if (nl >= L)    el = vl_l;
            }
            if (few_l) { fbL = fminf(fbL, hv); el = fbL; }

            float mean = 0.5f * (eu + el);
            float o = hv - mean;
            acc_m += mean * mean;
            acc_h += hv * hv;
            switch (r) {
                case 0: ov.x = o; break;
                case 1: ov.y = o; break;
                case 2: ov.z = o; break;
                default: ov.w = o; break;
            }
        }
        ((float4*)obase)[q] = ov;
    }
    o_m  = acc_m;
    o_h2 = acc_h;
}

__global__ void __launch_bounds__(NT, 1)
emd_kernel(const float* __restrict__ x, float* __restrict__ out)
{
    extern __shared__ unsigned char dynsm[];
    float* bufA = (float*)dynsm;      // LP2 floats
    float* bufB = bufA + LP2;         // LP2 floats

    __shared__ unsigned s_u[3 * NW];
    __shared__ float    s_f[NW + 1];
    __shared__ double   s_d[4 * NW];   // block-sum scratch
    __shared__ double   s_d2[16];      // grid flag-reduce scratch
    __shared__ int      s_flag;

    const int t   = threadIdx.x;
    const int lo  = t * CHUNK;
    const int row = blockIdx.x;

    const float* xr   = x + (size_t)row * L;
    float*       resr = g_res + (size_t)row * L;

    // res = x (re-initialized every launch: deterministic)
#pragma unroll
    for (int q = 0; q < 4; ++q)
        *(float4*)(resr + lo + 4 * q) = *(const float4*)(xr + lo + 4 * q);

    unsigned tag        = 1;   // per-launch phase tag (g_seq reset to 0 at kernel end)
    bool     outer_done = false;

    for (int im = 0; im < NIMF; ++im) {
        float* outim = out + ((size_t)im * BROWS + row) * L;
        if (outer_done) {
            float4 z = make_float4(0.f, 0.f, 0.f, 0.f);
#pragma unroll
            for (int q = 0; q < 4; ++q) *(float4*)(outim + lo + 4 * q) = z;
            continue;  // globally uniform -> tag counts stay consistent
        }

        float* hc = bufA;
        float* ho = bufB;
#pragma unroll
        for (int q = 0; q < 4; ++q)
            ((float4*)(hc + PH(lo)))[q] = *(const float4*)(resr + lo + 4 * q);
        __syncthreads();

        // ---- sifting (double-buffered) ----
        for (int it = 0; it < MAXIT; ++it) {
            float fm, fh2;
            sift_pass(hc, ho, s_u, s_f, fm, fh2);
            double sm = (double)fm, sh2 = (double)fh2;
            block_sum2_to0(sm, sh2, s_d);            // totals on t0
            if (t == 0) {
                double* p = &g_part[tag & 1][row][0];
                p[0] = sm; p[1] = sh2;
                __threadfence();
                ((volatile unsigned*)g_seq)[row] = tag;
            }
            if (t < 64) {
                volatile unsigned* sq = &g_seq[t];
                while (*sq < tag) {}
            }
            __threadfence();
            if (t < 64) {
                volatile double* p = &g_part[tag & 1][t][0];
                double a = p[0], b = p[1];
#pragma unroll
                for (int d = 16; d; d >>= 1) {
                    a += __shfl_down_sync(0xffffffffu, a, d);
                    b += __shfl_down_sync(0xffffffffu, b, d);
                }
                if ((t & 31) == 0) { s_d2[t >> 5] = a; s_d2[2 + (t >> 5)] = b; }
            }
            __syncthreads();
            if (t == 0) {
                double A = s_d2[0] + s_d2[1], Bs = s_d2[2] + s_d2[3];
                s_flag = (A / (Bs + 1e-8) < 0.05) ? 1 : 0;
            }
            tag++;
            __syncthreads();
            if (s_flag) break;            // converged: keep hc (pre-subtract), matching reference
            float* tmp = hc; hc = ho; ho = tmp;   // accept h - mean
        }

        // ---- emit IMF, update residual, global flatness check ----
        float ar = 0.f, ar2 = 0.f;
#pragma unroll
        for (int q = 0; q < 4; ++q) {
            float4 hv = ((const float4*)(hc + PH(lo)))[q];
            float4 rr = *(const float4*)(resr + lo + 4 * q);
            float4 nr;
            nr.x = rr.x - hv.x; nr.y = rr.y - hv.y;
            nr.z = rr.z - hv.z; nr.w = rr.w - hv.w;
            *(float4*)(outim + lo + 4 * q) = hv;
            *(float4*)(resr + lo + 4 * q)  = nr;
            ((float4*)(ho + PH(lo)))[q]    = nr;
            ar  += nr.x + nr.y + nr.z + nr.w;
            ar2 += nr.x * nr.x + nr.y * nr.y + nr.z * nr.z + nr.w * nr.w;
        }
        __syncthreads();
        float ad = 0.f, ad2 = 0.f;
        {
            float c16[CHUNK];
#pragma unroll
            for (int q = 0; q < 4; ++q)
                *(float4*)&c16[4 * q] = ((const float4*)(ho + PH(lo)))[q];
            float nb = (t < NT - 1) ? ho[PH(lo + CHUNK)] : 0.f;
#pragma unroll
            for (int j = 0; j < CHUNK; ++j) {
                float nx = (j < CHUNK - 1) ? c16[j + 1] : nb;
                if (lo + j < L - 1) {
                    float d = nx - c16[j];
                    ad  += d;
                    ad2 += d * d;
                }
            }
        }
        double Sd = (double)ad, Sd2 = (double)ad2;
        double Sr = (double)ar, Sr2 = (double)ar2;
        block_sum4_to0(Sd, Sd2, Sr, Sr2, s_d);       // totals on t0
        if (t == 0) {
            double* p = &g_part[tag & 1][row][0];
            p[0] = Sd; p[1] = Sd2; p[2] = Sr; p[3] = Sr2;
            __threadfence();
            ((volatile unsigned*)g_seq)[row] = tag;
        }
        if (t < 64) {
            volatile unsigned* sq = &g_seq[t];
            while (*sq < tag) {}
        }
        __threadfence();
        if (t < 64) {
            volatile double* p = &g_part[tag & 1][t][0];
            double a = p[0], b = p[1], c = p[2], e = p[3];
#pragma unroll
            for (int d = 16; d; d >>= 1) {
                a += __shfl_down_sync(0xffffffffu, a, d);
                b += __shfl_down_sync(0xffffffffu, b, d);
                c += __shfl_down_sync(0xffffffffu, c, d);
                e += __shfl_down_sync(0xffffffffu, e, d);
            }
            if ((t & 31) == 0) {
                int w = t >> 5;
                s_d2[4 * w + 0] = a; s_d2[4 * w + 1] = b;
                s_d2[4 * w + 2] = c; s_d2[4 * w + 3] = e;
            }
        }
        __syncthreads();
        if (t == 0) {
            double a = s_d2[0] + s_d2[4], b = s_d2[1] + s_d2[5];
            double c = s_d2[2] + s_d2[6], e = s_d2[3] + s_d2[7];
            double ndv = (double)BROWS * (double)(L - 1);
            double nrv = (double)BROWS * (double)L;
            double vard = (b - a * a / ndv) / (ndv - 1.0);
            double varr = (e - c * c / nrv) / (nrv - 1.0);
            s_flag = (vard < 0.05 * varr) ? 1 : 0;
        }
        tag++;
        __syncthreads();
        if (s_flag) outer_done = true;
    }

    // final residual
    float* outres = out + ((size_t)NIMF * BROWS + row) * L;
#pragma unroll
    for (int q = 0; q < 4; ++q)
        *(float4*)(outres + lo + 4 * q) = *(const float4*)(resr + lo + 4 * q);

    // ---- end-of-launch rendezvous + reset of g_seq for graph replays ----
    __syncthreads();
    if (t == 0) {
        __threadfence();
        atomicAdd(&g_count, 1u);
    }
    if (row == 0) {
        if (t == 0) {
            volatile unsigned* vc = &g_count;
            while (*vc < (unsigned)BROWS) {}
            __threadfence();
        }
        __syncthreads();
        if (t < BROWS) ((volatile unsigned*)g_seq)[t] = 0u;
        if (t == 0) g_count = 0u;
    }
}

extern "C" void kernel_launch(void* const* d_in, const int* in_sizes, int n_in,
                              void* d_out, int out_size) {
    (void)in_sizes; (void)n_in; (void)out_size;
    const size_t shmem = (size_t)(2 * LP2) * sizeof(float);
    cudaFuncSetAttribute(emd_kernel, cudaFuncAttributeMaxDynamicSharedMemorySize, (int)shmem);
    emd_kernel<<<BROWS, NT, shmem>>>((const float*)d_in[0], (float*)d_out);
}

// round 7
// speedup vs baseline: 1.1934x; 1.0374x over previous
#include <cuda_runtime.h>
#include <cstdint>

#define BROWS 64
#define L 16384
#define NT 1024
#define NW 32
#define CHUNK 16
#define NIMF 6
#define MAXIT 12
// pad 4 floats per 16 -> per-thread chunk stride = 20 words (80B): float4 phases conflict-free
#define LP2 (L + (L >> 2))
#define PH(i) ((i) + (((i) >> 4) << 2))

// -------- device-global scratch (allocation-free contract) --------
__device__ float    g_res[BROWS * L];
__device__ double   g_part[2][BROWS][4];
__device__ unsigned g_seq[BROWS];        // per-row phase tags (reset to 0 at kernel end)
__device__ unsigned g_count = 0;         // end-of-kernel rendezvous only

__device__ __forceinline__ float negInf() { return __int_as_float(0xff800000); }
__device__ __forceinline__ float posInf() { return __int_as_float(0x7f800000); }

// -------- fused block collectives: packed suffix-min, packed prefix-max, packed sum --------
__device__ __forceinline__ void fused_coll(unsigned vmin, unsigned vmax, unsigned vsum,
                                           unsigned* ubuf,
                                           unsigned& offn, unsigned& offl, unsigned& tot) {
    const int lane = threadIdx.x & 31, wid = threadIdx.x >> 5;
    unsigned imin = vmin, imax = vmax, s = vsum;
#pragma unroll
    for (int d = 1; d < 32; d <<= 1) {
        unsigned a = __shfl_down_sync(0xffffffffu, imin, d);
        if (lane + d < 32) imin = __vminu2(imin, a);
        unsigned b = __shfl_up_sync(0xffffffffu, imax, d);
        if (lane >= d) imax = __vmaxs2(imax, b);
        s += __shfl_xor_sync(0xffffffffu, s, d);
    }
    if (lane == 0)  { ubuf[wid] = imin; ubuf[2 * NW + wid] = s; }
    if (lane == 31) { ubuf[NW + wid] = imax; }
    __syncthreads();
    if (wid == 0) {
        unsigned wm = ubuf[lane];
        unsigned wx = ubuf[NW + lane];
        unsigned ws = ubuf[2 * NW + lane];
#pragma unroll
        for (int d = 1; d < 32; d <<= 1) {
            unsigned a = __shfl_down_sync(0xffffffffu, wm, d);
            if (lane + d < 32) wm = __vminu2(wm, a);
            unsigned b = __shfl_up_sync(0xffffffffu, wx, d);
            if (lane >= d) wx = __vmaxs2(wx, b);
            ws += __shfl_xor_sync(0xffffffffu, ws, d);
        }
        ubuf[lane] = wm;
        ubuf[NW + lane] = wx;
        if (lane == 0) ubuf[2 * NW] = ws;
    }
    __syncthreads();
    unsigned woffn = (wid < NW - 1) ? ubuf[wid + 1] : 0x40004000u;   // (L, L)
    unsigned lexn  = __shfl_down_sync(0xffffffffu, imin, 1);
    offn = (lane < 31) ? __vminu2(woffn, lexn) : woffn;
    unsigned woffl = (wid > 0) ? ubuf[NW + wid - 1] : 0xffffffffu;   // (-1, -1)
    unsigned lexl  = __shfl_up_sync(0xffffffffu, imax, 1);
    offl = (lane > 0) ? __vmaxs2(woffl, lexl) : woffl;
    tot = ubuf[2 * NW];
    __syncthreads();
}

// -------- float exclusive prefix-max / prefix-min (rare fallback path) --------
__device__ __forceinline__ float pmax_f_excl(float v, float* wbuf) {
    const int lane = threadIdx.x & 31, wid = threadIdx.x >> 5;
    float incl = v;
#pragma unroll
    for (int d = 1; d < 32; d <<= 1) {
        float u = __shfl_up_sync(0xffffffffu, incl, d);
        if (lane >= d) incl = fmaxf(incl, u);
    }
    if (lane == 31) wbuf[wid] = incl;
    __syncthreads();
    if (wid == 0) {
        float w = wbuf[lane];
#pragma unroll
        for (int d = 1; d < 32; d <<= 1) {
            float u = __shfl_up_sync(0xffffffffu, w, d);
            if (lane >= d) w = fmaxf(w, u);
        }
        wbuf[lane] = w;
    }
    __syncthreads();
    float woff = (wid > 0) ? wbuf[wid - 1] : negInf();
    float lex  = __shfl_up_sync(0xffffffffu, incl, 1);
    float ex   = (lane > 0) ? fmaxf(woff, lex) : woff;
    __syncthreads();
    return ex;
}

__device__ __forceinline__ float pmin_f_excl(float v, float* wbuf) {
    const int lane = threadIdx.x & 31, wid = threadIdx.x >> 5;
    float incl = v;
#pragma unroll
    for (int d = 1; d < 32; d <<= 1) {
        float u = __shfl_up_sync(0xffffffffu, incl, d);
        if (lane >= d) incl = fminf(incl, u);
    }
    if (lane == 31) wbuf[wid] = incl;
    __syncthreads();
    if (wid == 0) {
        float w = wbuf[lane];
#pragma unroll
        for (int d = 1; d < 32; d <<= 1) {
            float u = __shfl_up_sync(0xffffffffu, w, d);
            if (lane >= d) w = fminf(w, u);
        }
        wbuf[lane] = w;
    }
    __syncthreads();
    float woff = (wid > 0) ? wbuf[wid - 1] : posInf();
    float lex  = __shfl_up_sync(0xffffffffu, incl, 1);
    float ex   = (lane > 0) ? fminf(woff, lex) : woff;
    __syncthreads();
    return ex;
}

// -------- block sums: totals valid on thread 0 only (no broadcast syncs) --------
__device__ __forceinline__ void block_sum2_to0(double& a, double& b, double* wbuf) {
#pragma unroll
    for (int d = 16; d; d >>= 1) {
        a += __shfl_down_sync(0xffffffffu, a, d);
        b += __shfl_down_sync(0xffffffffu, b, d);
    }
    const int lane = threadIdx.x & 31, wid = threadIdx.x >> 5;
    if (lane == 0) { wbuf[wid] = a; wbuf[NW + wid] = b; }
    __syncthreads();
    if (wid == 0) {
        double wa = wbuf[lane], wb = wbuf[NW + lane];
#pragma unroll
        for (int d = 16; d; d >>= 1) {
            wa += __shfl_down_sync(0xffffffffu, wa, d);
            wb += __shfl_down_sync(0xffffffffu, wb, d);
        }
        a = wa; b = wb;   // meaningful on lane 0 (== t0)
    }
}

__device__ __forceinline__ void block_sum4_to0(double& a, double& b, double& c, double& e,
                                               double* wbuf) {
#pragma unroll
    for (int d = 16; d; d >>= 1) {
        a += __shfl_down_sync(0xffffffffu, a, d);
        b += __shfl_down_sync(0xffffffffu, b, d);
        c += __shfl_down_sync(0xffffffffu, c, d);
        e += __shfl_down_sync(0xffffffffu, e, d);
    }
    const int lane = threadIdx.x & 31, wid = threadIdx.x >> 5;
    if (lane == 0) {
        wbuf[wid] = a; wbuf[NW + wid] = b;
        wbuf[2 * NW + wid] = c; wbuf[3 * NW + wid] = e;
    }
    __syncthreads();
    if (wid == 0) {
        double wa = wbuf[lane], wb = wbuf[NW + lane];
        double wc = wbuf[2 * NW + lane], we = wbuf[3 * NW + lane];
#pragma unroll
        for (int d = 16; d; d >>= 1) {
            wa += __shfl_down_sync(0xffffffffu, wa, d);
            wb += __shfl_down_sync(0xffffffffu, wb, d);
            wc += __shfl_down_sync(0xffffffffu, wc, d);
            we += __shfl_down_sync(0xffffffffu, we, d);
        }
        a = wa; b = wb; c = wc; e = we;   // meaningful on lane 0 (== t0)
    }
}

// -------- one fused sifting pass (R3-exact numerics: exact div + fp32 sd partials) --------
__device__ void sift_pass(const float* __restrict__ hc, float* __restrict__ ho,
                          unsigned* ubuf, float* fbuf,
                          float& o_m, float& o_h2)
{
    const int t  = threadIdx.x;
    const int lo = t * CHUNK;
    const float* cbase = hc + PH(lo);

    // ---- walk A: build peak-position bitmasks for both envelopes ----
    float h16[CHUNK];
#pragma unroll
    for (int q = 0; q < 4; ++q)
        *(float4*)&h16[4 * q] = ((const float4*)cbase)[q];
    float prev  = (t > 0)      ? hc[PH(lo - 1)]     : 0.f;
    float nextB = (t < NT - 1) ? hc[PH(lo + CHUNK)] : 0.f;

    unsigned mU = 0, mL = 0;
#pragma unroll
    for (int j = 0; j < CHUNK; ++j) {
        float cur = h16[j];
        float nxt = (j < CHUNK - 1) ? h16[j + 1] : nextB;
        mU |= (unsigned)((prev < cur) & (cur > nxt)) << j;
        mL |= (unsigned)((prev > cur) & (cur < nxt)) << j;
        prev = cur;
    }
    if (t == 0)      { mU &= ~1u;     mL &= ~1u;     }
    if (t == NT - 1) { mU &= 0x7fffu; mL &= 0x7fffu; }

    int run_u = mU ? lo + (__ffs(mU) - 1) : L;
    int run_l = mL ? lo + (__ffs(mL) - 1) : L;
    int cm_u  = mU ? lo + (31 - __clz((int)mU)) : -1;
    int cm_l  = mL ? lo + (31 - __clz((int)mL)) : -1;
    unsigned cnt = (unsigned)__popc(mU) | ((unsigned)__popc(mL) << 16);

    unsigned offn, offl, tot;
    fused_coll((unsigned)run_u | ((unsigned)run_l << 16),
               ((unsigned)cm_u & 0xffffu) | (((unsigned)cm_l & 0xffffu) << 16),
               cnt, ubuf, offn, offl, tot);

    const int  off_nu = (int)(offn & 0xffffu);
    const int  off_nl = (int)(offn >> 16);
    const int  off_lu = (int)(short)(offl & 0xffffu);
    const int  off_ll = (int)(short)(offl >> 16);
    const bool few_u  = (tot & 0xffffu) < 2u;   // block-uniform
    const bool few_l  = (tot >> 16)     < 2u;   // block-uniform

    float fbU = negInf(), fbL = posInf();
    if (few_u) {
        float cm = negInf();
#pragma unroll
        for (int j = 0; j < CHUNK; ++j) cm = fmaxf(cm, h16[j]);
        fbU = pmax_f_excl(cm, fbuf);
    }
    if (few_l) {
        float cm = posInf();
#pragma unroll
        for (int j = 0; j < CHUNK; ++j) cm = fminf(cm, h16[j]);
        fbL = pmin_f_excl(cm, fbuf);
    }

    // ---- walk B: per-element exact interpolation (bitwise-matching reference) ----
    int   runl_u = off_lu, runl_l = off_ll;
    float vl_u = hc[PH(max(runl_u, 0))];
    float vl_l = hc[PH(max(runl_l, 0))];
    int   cur_nu = -0x40000000, cur_nl = -0x40000000;
    float vr_u = 0.f, vr_l = 0.f;
    float acc_m = 0.f, acc_h = 0.f;
    float* obase = ho + PH(lo);

#pragma unroll
    for (int q = 0; q < 4; ++q) {
        float4 ov;
#pragma unroll
        for (int r = 0; r < 4; ++r) {
            const int j = 4 * q + r;
            const int i = lo + j;
            const float hv = h16[j];

            if ((mU >> j) & 1u) { runl_u = i; vl_u = hv; }
            unsigned remU = mU >> j;
            int nu = remU ? i + (__ffs(remU) - 1) : off_nu;
            if (nu != cur_nu) { cur_nu = nu; vr_u = hc[PH(min(nu, L - 1))]; }
            float eu;
            {
                int den = nu - runl_u;
                eu = (den > 0) ? vl_u + ((float)(i - runl_u) / (float)den) * (vr_u - vl_u)
                               : vl_u;
                if (runl_u < 0) eu = vr_u;   // left of first peak
                if (nu >= L)    eu = vl_u;   // right of last peak
            }
            if (few_u) { fbU = fmaxf(fbU, hv); eu = fbU; }

            if ((mL >> j) & 1u) { runl_l = i; vl_l = hv; }
            unsigned remL = mL >> j;
            int nl = remL ? i + (__ffs(remL) - 1) : off_nl;
            if (nl != cur_nl) { cur_nl = nl; vr_l = hc[PH(min(nl, L - 1))]; }
            float el;
            {
                int den = nl - runl_l;
                el = (den > 0) ? vl_l + ((float)(i - runl_l) / (float)den) * (vr_l - vl_l)
                               : vl_l;
                if (runl_l < 0) el = vr_l;
                if (nl >= L)    el = vl_l;
            }
            if (few_l) { fbL = fminf(fbL, hv); el = fbL; }

            float mean = 0.5f * (eu + el);
            float o = hv - mean;
            acc_m += mean * mean;
            acc_h += hv * hv;
            switch (r) {
                case 0: ov.x = o; break;
                case 1: ov.y = o; break;
                case 2: ov.z = o; break;
                default: ov.w = o; break;
            }
        }
        ((float4*)obase)[q] = ov;
    }
    o_m  = acc_m;
    o_h2 = acc_h;
}

__global__ void __launch_bounds__(NT, 1)
emd_kernel(const float* __restrict__ x, float* __restrict__ out)
{
    extern __shared__ unsigned char dynsm[];
    float* bufA = (float*)dynsm;      // LP2 floats
    float* bufB = bufA + LP2;         // LP2 floats

    __shared__ unsigned s_u[3 * NW];
    __shared__ float    s_f[NW + 1];
    __shared__ double   s_d[4 * NW];   // block-sum scratch
    __shared__ double   s_d2[16];      // grid flag-reduce scratch
    __shared__ int      s_flag;

    const int t   = threadIdx.x;
    const int lo  = t * CHUNK;
    const int row = blockIdx.x;

    const float* xr   = x + (size_t)row * L;
    float*       resr = g_res + (size_t)row * L;

    // res = x (re-initialized every launch: deterministic)
#pragma unroll
    for (int q = 0; q < 4; ++q)
        *(float4*)(resr + lo + 4 * q) = *(const float4*)(xr + lo + 4 * q);

    unsigned tag        = 1;   // per-launch phase tag (g_seq reset to 0 at kernel end)
    bool     outer_done = false;

    for (int im = 0; im < NIMF; ++im) {
        float* outim = out + ((size_t)im * BROWS + row) * L;
        if (outer_done) {
            float4 z = make_float4(0.f, 0.f, 0.f, 0.f);
#pragma unroll
            for (int q = 0; q < 4; ++q) *(float4*)(outim + lo + 4 * q) = z;
            continue;  // globally uniform -> tag counts stay consistent
        }

        float* hc = bufA;
        float* ho = bufB;
#pragma unroll
        for (int q = 0; q < 4; ++q)
            ((float4*)(hc + PH(lo)))[q] = *(const float4*)(resr + lo + 4 * q);
        __syncthreads();

        // ---- sifting (double-buffered) ----
        for (int it = 0; it < MAXIT; ++it) {
            float fm, fh2;
            sift_pass(hc, ho, s_u, s_f, fm, fh2);
            double sm = (double)fm, sh2 = (double)fh2;
            block_sum2_to0(sm, sh2, s_d);            // totals on t0
            if (t == 0) {
                double* p = &g_part[tag & 1][row][0];
                p[0] = sm; p[1] = sh2;
                __threadfence();
                ((volatile unsigned*)g_seq)[row] = tag;
            }
            if (t < 64) {
                volatile unsigned* sq = &g_seq[t];
                while (*sq < tag) {}
            }
            __threadfence();
            if (t < 64) {
                volatile double* p = &g_part[tag & 1][t][0];
                double a = p[0], b = p[1];
#pragma unroll
                for (int d = 16; d; d >>= 1) {
                    a += __shfl_down_sync(0xffffffffu, a, d);
                    b += __shfl_down_sync(0xffffffffu, b, d);
                }
                if ((t & 31) == 0) { s_d2[t >> 5] = a; s_d2[2 + (t >> 5)] = b; }
            }
            __syncthreads();
            if (t == 0) {
                double A = s_d2[0] + s_d2[1], Bs = s_d2[2] + s_d2[3];
                s_flag = (A / (Bs + 1e-8) < 0.05) ? 1 : 0;
            }
            tag++;
            __syncthreads();
            if (s_flag) break;            // converged: keep hc (pre-subtract), matching reference
            float* tmp = hc; hc = ho; ho = tmp;   // accept h - mean
        }

        // ---- emit IMF, update residual, global flatness check ----
        float ar = 0.f, ar2 = 0.f;
#pragma unroll
        for (int q = 0; q < 4; ++q) {
            float4 hv = ((const float4*)(hc + PH(lo)))[q];
            float4 rr = *(const float4*)(resr + lo + 4 * q);
            float4 nr;
            nr.x = rr.x - hv.x; nr.y = rr.y - hv.y;
            nr.z = rr.z - hv.z; nr.w = rr.w - hv.w;
            *(float4*)(outim + lo + 4 * q) = hv;
            *(float4*)(resr + lo + 4 * q)  = nr;
            ((float4*)(ho + PH(lo)))[q]    = nr;
            ar  += nr.x + nr.y + nr.z + nr.w;
            ar2 += nr.x * nr.x + nr.y * nr.y + nr.z * nr.z + nr.w * nr.w;
        }
        __syncthreads();
        float ad = 0.f, ad2 = 0.f;
        {
            float c16[CHUNK];
#pragma unroll
            for (int q = 0; q < 4; ++q)
                *(float4*)&c16[4 * q] = ((const float4*)(ho + PH(lo)))[q];
            float nb = (t < NT - 1) ? ho[PH(lo + CHUNK)] : 0.f;
#pragma unroll
            for (int j = 0; j < CHUNK; ++j) {
                float nx = (j < CHUNK - 1) ? c16[j + 1] : nb;
                if (lo + j < L - 1) {
                    float d = nx - c16[j];
                    ad  += d;
                    ad2 += d * d;
                }
            }
        }
        double Sd = (double)ad, Sd2 = (double)ad2;
        double Sr = (double)ar, Sr2 = (double)ar2;
        block_sum4_to0(Sd, Sd2, Sr, Sr2, s_d);       // totals on t0
        if (t == 0) {
            double* p = &g_part[tag & 1][row][0];
            p[0] = Sd; p[1] = Sd2; p[2] = Sr; p[3] = Sr2;
            __threadfence();
            ((volatile unsigned*)g_seq)[row] = tag;
        }
        if (t < 64) {
            volatile unsigned* sq = &g_seq[t];
            while (*sq < tag) {}
        }
        __threadfence();
        if (t < 64) {
            volatile double* p = &g_part[tag & 1][t][0];
            double a = p[0], b = p[1], c = p[2], e = p[3];
#pragma unroll
            for (int d = 16; d; d >>= 1) {
                a += __shfl_down_sync(0xffffffffu, a, d);
                b += __shfl_down_sync(0xffffffffu, b, d);
                c += __shfl_down_sync(0xffffffffu, c, d);
                e += __shfl_down_sync(0xffffffffu, e, d);
            }
            if ((t & 31) == 0) {
                int w = t >> 5;
                s_d2[4 * w + 0] = a; s_d2[4 * w + 1] = b;
                s_d2[4 * w + 2] = c; s_d2[4 * w + 3] = e;
            }
        }
        __syncthreads();
        if (t == 0) {
            double a = s_d2[0] + s_d2[4], b = s_d2[1] + s_d2[5];
            double c = s_d2[2] + s_d2[6], e = s_d2[3] + s_d2[7];
            double ndv = (double)BROWS * (double)(L - 1);
            double nrv = (double)BROWS * (double)L;
            double vard = (b - a * a / ndv) / (ndv - 1.0);
            double varr = (e - c * c / nrv) / (nrv - 1.0);
            s_flag = (vard < 0.05 * varr) ? 1 : 0;
        }
        tag++;
        __syncthreads();
        if (s_flag) outer_done = true;
    }

    // final residual
    float* outres = out + ((size_t)NIMF * BROWS + row) * L;
#pragma unroll
    for (int q = 0; q < 4; ++q)
        *(float4*)(outres + lo + 4 * q) = *(const float4*)(resr + lo + 4 * q);

    // ---- end-of-launch rendezvous + reset of g_seq for graph replays ----
    __syncthreads();
    if (t == 0) {
        __threadfence();
        atomicAdd(&g_count, 1u);
    }
    if (row == 0) {
        if (t == 0) {
            volatile unsigned* vc = &g_count;
            while (*vc < (unsigned)BROWS) {}
            __threadfence();
        }
        __syncthreads();
        if (t < BROWS) ((volatile unsigned*)g_seq)[t] = 0u;
        if (t == 0) g_count = 0u;
    }
}

extern "C" void kernel_launch(void* const* d_in, const int* in_sizes, int n_in,
                              void* d_out, int out_size) {
    (void)in_sizes; (void)n_in; (void)out_size;
    const size_t shmem = (size_t)(2 * LP2) * sizeof(float);
    cudaFuncSetAttribute(emd_kernel, cudaFuncAttributeMaxDynamicSharedMemorySize, (int)shmem);
    emd_kernel<<<BROWS, NT, shmem>>>((const float*)d_in[0], (float*)d_out);
}

// round 8
// speedup vs baseline: 1.2359x; 1.0356x over previous
#include <cuda_runtime.h>
#include <cstdint>

#define BROWS 64
#define L 16384
#define HALF 8192
#define NCTA 128
#define NT 1024
#define NW 32
#define CHUNK 8
#define NIMF 6
#define MAXIT 12
#define LPH (HALF + (HALF >> 1))           // 12288 words per buffer
#define PH(i) ((i) + (((i) >> 3) << 2))    // pad 4 words per 8: stride-12 chunks, conflict-free

// totals slots in ubuf
#define T_RUN (5 * NW + 0)
#define T_CM  (5 * NW + 1)
#define T_CNT (5 * NW + 2)
#define T_MAX (5 * NW + 3)
#define T_MIN (5 * NW + 4)

__device__ float    g_res[BROWS * L];
__device__ double   g_part[2][NCTA][4];
__device__ unsigned g_seq[NCTA];
__device__ unsigned g_count = 0;

__device__ __forceinline__ float negInf() { return __int_as_float(0xff800000); }
__device__ __forceinline__ float posInf() { return __int_as_float(0x7f800000); }

#define CLUSTER_SYNC() do { \
    asm volatile("barrier.cluster.arrive.aligned;" ::: "memory"); \
    asm volatile("barrier.cluster.wait.aligned;" ::: "memory"); \
} while (0)

__device__ __forceinline__ float dsmem_ld(const float* p, unsigned rank) {
    uint32_t a = (uint32_t)__cvta_generic_to_shared(p), r; float v;
    asm volatile("mapa.shared::cluster.u32 %0, %1, %2;" : "=r"(r) : "r"(a), "r"(rank));
    asm volatile("ld.shared::cluster.f32 %0, [%1];" : "=f"(v) : "r"(r) : "memory");
    return v;
}

// fused collectives + CTA totals (totals left in ubuf[T_*])
__device__ __forceinline__ void fused_coll(unsigned vmin, unsigned vmax, unsigned vsum,
                                           float cmx, float cmn, unsigned* ubuf,
                                           unsigned& offn, unsigned& offl) {
    const int lane = threadIdx.x & 31, wid = threadIdx.x >> 5;
    unsigned imin = vmin, imax = vmax, s = vsum;
    float fx = cmx, fn = cmn;
#pragma unroll
    for (int d = 1; d < 32; d <<= 1) {
        unsigned a = __shfl_down_sync(0xffffffffu, imin, d);
        if (lane + d < 32) imin = __vminu2(imin, a);
        unsigned b = __shfl_up_sync(0xffffffffu, imax, d);
        if (lane >= d) imax = __vmaxs2(imax, b);
        s += __shfl_xor_sync(0xffffffffu, s, d);
        fx = fmaxf(fx, __shfl_xor_sync(0xffffffffu, fx, d));
        fn = fminf(fn, __shfl_xor_sync(0xffffffffu, fn, d));
    }
    if (lane == 0) {
        ubuf[wid] = imin; ubuf[2 * NW + wid] = s;
        ubuf[3 * NW + wid] = __float_as_uint(fx);
        ubuf[4 * NW + wid] = __float_as_uint(fn);
    }
    if (lane == 31) ubuf[NW + wid] = imax;
    __syncthreads();
    if (wid == 0) {
        unsigned wm = ubuf[lane], wx = ubuf[NW + lane], ws = ubuf[2 * NW + lane];
        float wfx = __uint_as_float(ubuf[3 * NW + lane]);
        float wfn = __uint_as_float(ubuf[4 * NW + lane]);
#pragma unroll
        for (int d = 1; d < 32; d <<= 1) {
            unsigned a = __shfl_down_sync(0xffffffffu, wm, d);
            if (lane + d < 32) wm = __vminu2(wm, a);
            unsigned b = __shfl_up_sync(0xffffffffu, wx, d);
            if (lane >= d) wx = __vmaxs2(wx, b);
            ws += __shfl_xor_sync(0xffffffffu, ws, d);
            wfx = fmaxf(wfx, __shfl_xor_sync(0xffffffffu, wfx, d));
            wfn = fminf(wfn, __shfl_xor_sync(0xffffffffu, wfn, d));
        }
        ubuf[lane] = wm; ubuf[NW + lane] = wx;
        if (lane == 0) {
            ubuf[T_RUN] = wm; ubuf[T_CNT] = ws;
            ubuf[T_MAX] = __float_as_uint(wfx);
            ubuf[T_MIN] = __float_as_uint(wfn);
        }
        if (lane == 31) ubuf[T_CM] = wx;
    }
    __syncthreads();
    unsigned woffn = (wid < NW - 1) ? ubuf[wid + 1] : 0x40004000u;
    unsigned lexn  = __shfl_down_sync(0xffffffffu, imin, 1);
    offn = (lane < 31) ? __vminu2(woffn, lexn) : woffn;
    unsigned woffl = (wid > 0) ? ubuf[NW + wid - 1] : 0xffffffffu;
    unsigned lexl  = __shfl_up_sync(0xffffffffu, imax, 1);
    offl = (lane > 0) ? __vmaxs2(woffl, lexl) : woffl;
}

__device__ __forceinline__ float pmax_f_excl(float v, float* wbuf) {
    const int lane = threadIdx.x & 31, wid = threadIdx.x >> 5;
    float incl = v;
#pragma unroll
    for (int d = 1; d < 32; d <<= 1) {
        float u = __shfl_up_sync(0xffffffffu, incl, d);
        if (lane >= d) incl = fmaxf(incl, u);
    }
    if (lane == 31) wbuf[wid] = incl;
    __syncthreads();
    if (wid == 0) {
        float w = wbuf[lane];
#pragma unroll
        for (int d = 1; d < 32; d <<= 1) {
            float u = __shfl_up_sync(0xffffffffu, w, d);
            if (lane >= d) w = fmaxf(w, u);
        }
        wbuf[lane] = w;
    }
    __syncthreads();
    float woff = (wid > 0) ? wbuf[wid - 1] : negInf();
    float lex  = __shfl_up_sync(0xffffffffu, incl, 1);
    float ex   = (lane > 0) ? fmaxf(woff, lex) : woff;
    __syncthreads();
    return ex;
}

__device__ __forceinline__ float pmin_f_excl(float v, float* wbuf) {
    const int lane = threadIdx.x & 31, wid = threadIdx.x >> 5;
    float incl = v;
#pragma unroll
    for (int d = 1; d < 32; d <<= 1) {
        float u = __shfl_up_sync(0xffffffffu, incl, d);
        if (lane >= d) incl = fminf(incl, u);
    }
    if (lane == 31) wbuf[wid] = incl;
    __syncthreads();
    if (wid == 0) {
        float w = wbuf[lane];
#pragma unroll
        for (int d = 1; d < 32; d <<= 1) {
            float u = __shfl_up_sync(0xffffffffu, w, d);
            if (lane >= d) w = fminf(w, u);
        }
        wbuf[lane] = w;
    }
    __syncthreads();
    float woff = (wid > 0) ? wbuf[wid - 1] : posInf();
    float lex  = __shfl_up_sync(0xffffffffu, incl, 1);
    float ex   = (lane > 0) ? fminf(woff, lex) : woff;
    __syncthreads();
    return ex;
}

__device__ __forceinline__ void block_sum2_to0(double& a, double& b, double* wbuf) {
#pragma unroll
    for (int d = 16; d; d >>= 1) {
        a += __shfl_down_sync(0xffffffffu, a, d);
        b += __shfl_down_sync(0xffffffffu, b, d);
    }
    const int lane = threadIdx.x & 31, wid = threadIdx.x >> 5;
    if (lane == 0) { wbuf[wid] = a; wbuf[NW + wid] = b; }
    __syncthreads();
    if (wid == 0) {
        double wa = wbuf[lane], wb = wbuf[NW + lane];
#pragma unroll
        for (int d = 16; d; d >>= 1) {
            wa += __shfl_down_sync(0xffffffffu, wa, d);
            wb += __shfl_down_sync(0xffffffffu, wb, d);
        }
        a = wa; b = wb;
    }
}

__device__ __forceinline__ void block_sum4_to0(double& a, double& b, double& c, double& e,
                                               double* wbuf) {
#pragma unroll
    for (int d = 16; d; d >>= 1) {
        a += __shfl_down_sync(0xffffffffu, a, d);
        b += __shfl_down_sync(0xffffffffu, b, d);
        c += __shfl_down_sync(0xffffffffu, c, d);
        e += __shfl_down_sync(0xffffffffu, e, d);
    }
    const int lane = threadIdx.x & 31, wid = threadIdx.x >> 5;
    if (lane == 0) {
        wbuf[wid] = a; wbuf[NW + wid] = b;
        wbuf[2 * NW + wid] = c; wbuf[3 * NW + wid] = e;
    }
    __syncthreads();
    if (wid == 0) {
        double wa = wbuf[lane], wb = wbuf[NW + lane];
        double wc = wbuf[2 * NW + lane], we = wbuf[3 * NW + lane];
#pragma unroll
        for (int d = 16; d; d >>= 1) {
            wa += __shfl_down_sync(0xffffffffu, wa, d);
            wb += __shfl_down_sync(0xffffffffu, wb, d);
            wc += __shfl_down_sync(0xffffffffu, wc, d);
            we += __shfl_down_sync(0xffffffffu, we, d);
        }
        a = wa; b = wb; c = wc; e = we;
    }
}

// one sifting pass over a half-row; peer coupling via DSMEM mailbox
__device__ void sift_pass(const float* __restrict__ hc, float* __restrict__ ho, int sub,
                          unsigned* ubuf, float* fbuf, float* s_mb, float* s_peer,
                          float& o_m, float& o_h2)
{
    const int t = threadIdx.x;
    const int lo = t * CHUNK;
    const int loG = sub * HALF, hiG = loG + HALF;
    const int gbase = loG + lo;
    const unsigned peer = (unsigned)(sub ^ 1);

    float h8[CHUNK];
    const float* cbase = hc + PH(lo);
    *(float4*)&h8[0] = ((const float4*)cbase)[0];
    *(float4*)&h8[4] = ((const float4*)cbase)[1];

    float prev, nextB;
    if (t > 0)            prev  = hc[PH(lo - 1)];
    else                  prev  = (sub == 1) ? dsmem_ld(&hc[PH(HALF - 1)], 0u) : 0.f;
    if (t < NT - 1)       nextB = hc[PH(lo + CHUNK)];
    else                  nextB = (sub == 0) ? dsmem_ld(&hc[PH(0)], 1u) : 0.f;

    unsigned mU = 0, mL = 0;
    float cmx = negInf(), cmn = posInf();
#pragma unroll
    for (int j = 0; j < CHUNK; ++j) {
        float cur = h8[j];
        float nxt = (j < CHUNK - 1) ? h8[j + 1] : nextB;
        mU |= (unsigned)((prev < cur) & (cur > nxt)) << j;
        mL |= (unsigned)((prev > cur) & (cur < nxt)) << j;
        cmx = fmaxf(cmx, cur); cmn = fminf(cmn, cur);
        prev = cur;
    }
    if (sub == 0 && t == 0)      { mU &= ~1u;   mL &= ~1u;   }
    if (sub == 1 && t == NT - 1) { mU &= 0x7fu; mL &= 0x7fu; }

    int run_u = mU ? gbase + (__ffs(mU) - 1) : L;
    int run_l = mL ? gbase + (__ffs(mL) - 1) : L;
    int cm_u  = mU ? gbase + (31 - __clz((int)mU)) : -1;
    int cm_l  = mL ? gbase + (31 - __clz((int)mL)) : -1;
    unsigned cnt = (unsigned)__popc(mU) | ((unsigned)__popc(mL) << 16);

    unsigned offn, offl;
    fused_coll((unsigned)run_u | ((unsigned)run_l << 16),
               ((unsigned)cm_u & 0xffffu) | (((unsigned)cm_l & 0xffffu) << 16),
               cnt, cmx, cmn, ubuf, offn, offl);

    if (t == 0) {
        unsigned tr = ubuf[T_RUN], tc = ubuf[T_CM];
        int fu = (int)(tr & 0xffffu), fl2 = (int)(tr >> 16);
        int lu = (int)(short)(tc & 0xffffu), ll = (int)(short)(tc >> 16);
        s_mb[0] = __uint_as_float(tr);
        s_mb[1] = __uint_as_float(tc);
        s_mb[2] = __uint_as_float(ubuf[T_CNT]);
        s_mb[3] = __uint_as_float(ubuf[T_MAX]);
        s_mb[4] = __uint_as_float(ubuf[T_MIN]);
        s_mb[5] = (fu  < L)  ? hc[PH(fu  - loG)] : 0.f;
        s_mb[6] = (fl2 < L)  ? hc[PH(fl2 - loG)] : 0.f;
        s_mb[7] = (lu  >= 0) ? hc[PH(lu  - loG)] : 0.f;
        s_mb[8] = (ll  >= 0) ? hc[PH(ll  - loG)] : 0.f;
    }
    __syncthreads();
    CLUSTER_SYNC();
    if (t < 9) s_peer[t] = dsmem_ld(&s_mb[t], peer);
    __syncthreads();

    unsigned totc = ubuf[T_CNT] + __float_as_uint(s_peer[2]);
    if (sub == 0) offn = __vminu2(offn, __float_as_uint(s_peer[0]));
    else          offl = __vmaxs2(offl, __float_as_uint(s_peer[1]));

    const int  off_nu = (int)(offn & 0xffffu);
    const int  off_nl = (int)(offn >> 16);
    const bool few_u  = (totc & 0xffffu) < 2u;
    const bool few_l  = (totc >> 16)     < 2u;

    float fbU = negInf(), fbL = posInf();
    if (few_u) {
        float ex = pmax_f_excl(cmx, fbuf);
        fbU = (sub == 1) ? fmaxf(ex, __uint_as_float(__float_as_uint(s_peer[3]))) : ex;
    }
    if (few_l) {
        float ex = pmin_f_excl(cmn, fbuf);
        fbL = (sub == 1) ? fminf(ex, __uint_as_float(__float_as_uint(s_peer[4]))) : ex;
    }

    int   runl_u = (int)(short)(offl & 0xffffu);
    int   runl_l = (int)(short)(offl >> 16);
    float pFPU = s_peer[5], pFPL = s_peer[6], pLPU = s_peer[7], pLPL = s_peer[8];
    float vl_u = (runl_u >= loG) ? hc[PH(runl_u - loG)] : pLPU;
    float vl_l = (runl_l >= loG) ? hc[PH(runl_l - loG)] : pLPL;
    int   cur_nu = -0x40000000, cur_nl = -0x40000000;
    float vr_u = 0.f, vr_l = 0.f;
    float acc_m = 0.f, acc_h = 0.f;
    float* obase = ho + PH(lo);

#pragma unroll
    for (int q = 0; q < 2; ++q) {
        float4 ov;
#pragma unroll
        for (int r = 0; r < 4; ++r) {
            const int j = 4 * q + r;
            const int gi = gbase + j;
            const float hv = h8[j];

            if ((mU >> j) & 1u) { runl_u = gi; vl_u = hv; }
            unsigned remU = mU >> j;
            int nu = remU ? gi + (__ffs(remU) - 1) : off_nu;
            if (nu != cur_nu) { cur_nu = nu; vr_u = (nu < hiG) ? hc[PH(nu - loG)] : pFPU; }
            float eu;
            {
                int den = nu - runl_u;
                eu = (den > 0) ? vl_u + ((float)(gi - runl_u) / (float)den) * (vr_u - vl_u)
                               : vl_u;
                if (runl_u < 0) eu = vr_u;
                if (nu >= L)    eu = vl_u;
            }
            if (few_u) { fbU = fmaxf(fbU, hv); eu = fbU; }

            if ((mL >> j) & 1u) { runl_l = gi; vl_l = hv; }
            unsigned remL = mL >> j;
            int nl = remL ? gi + (__ffs(remL) - 1) : off_nl;
            if (nl != cur_nl) { cur_nl = nl; vr_l = (nl < hiG) ? hc[PH(nl - loG)] : pFPL; }
            float el;
            {
                int den = nl - runl_l;
                el = (den > 0) ? vl_l + ((float)(gi - runl_l) / (float)den) * (vr_l - vl_l)
                               : vl_l;
                if (runl_l < 0) el = vr_l;
                if (nl >= L)    el = vl_l;
            }
            if (few_l) { fbL = fminf(fbL, hv); el = fbL; }

            float mean = 0.5f * (eu + el);
            float o = hv - mean;
            acc_m += mean * mean;
            acc_h += hv * hv;
            switch (r) {
                case 0: ov.x = o; break;
                case 1: ov.y = o; break;
                case 2: ov.z = o; break;
                default: ov.w = o; break;
            }
        }
        ((float4*)obase)[q] = ov;
    }
    o_m = acc_m; o_h2 = acc_h;
}

__global__ void __launch_bounds__(NT, 1) __cluster_dims__(2, 1, 1)
emd_kernel(const float* __restrict__ x, float* __restrict__ out)
{
    extern __shared__ unsigned char dynsm[];
    float* bufA = (float*)dynsm;
    float* bufB = bufA + LPH;

    __shared__ unsigned s_u[5 * NW + 5];
    __shared__ float    s_f[NW + 1];
    __shared__ float    s_mb[10];
    __shared__ float    s_peer[10];
    __shared__ double   s_d[4 * NW];
    __shared__ double   s_d2[16];
    __shared__ int      s_flag;

    const int t    = threadIdx.x;
    const int lo   = t * CHUNK;
    const int cta  = blockIdx.x;
    const int row  = cta >> 1;
    unsigned rk;
    asm("mov.u32 %0, %%cluster_ctarank;" : "=r"(rk));
    const int sub = (int)rk;

    const float* xr   = x + (size_t)row * L + sub * HALF;
    float*       resr = g_res + (size_t)row * L + sub * HALF;

#pragma unroll
    for (int q = 0; q < 2; ++q)
        *(float4*)(resr + lo + 4 * q) = *(const float4*)(xr + lo + 4 * q);

    unsigned tag = 1;
    bool outer_done = false;

    for (int im = 0; im < NIMF; ++im) {
        float* outim = out + ((size_t)im * BROWS + row) * L + sub * HALF;
        if (outer_done) {
            float4 z = make_float4(0.f, 0.f, 0.f, 0.f);
#pragma unroll
            for (int q = 0; q < 2; ++q) *(float4*)(outim + lo + 4 * q) = z;
            continue;  // globally uniform
        }

        float* hc = bufA;
        float* ho = bufB;
#pragma unroll
        for (int q = 0; q < 2; ++q)
            ((float4*)(hc + PH(lo)))[q] = *(const float4*)(resr + lo + 4 * q);
        __syncthreads();
        CLUSTER_SYNC();   // peer hc ready before halo reads

        for (int it = 0; it < MAXIT; ++it) {
            float fm, fh2;
            sift_pass(hc, ho, sub, s_u, s_f, s_mb, s_peer, fm, fh2);
            double sm = (double)fm, sh2 = (double)fh2;
            block_sum2_to0(sm, sh2, s_d);
            if (t == 0) {
                double* p = &g_part[tag & 1][cta][0];
                p[0] = sm; p[1] = sh2;
                __threadfence();
                ((volatile unsigned*)g_seq)[cta] = tag;
            }
            if (t < NCTA) {
                volatile unsigned* sq = &g_seq[t];
                while (*sq < tag) {}
            }
            __threadfence();
            if (t < NCTA) {
                volatile double* p = &g_part[tag & 1][t][0];
                double a = p[0], b = p[1];
#pragma unroll
                for (int d = 16; d; d >>= 1) {
                    a += __shfl_down_sync(0xffffffffu, a, d);
                    b += __shfl_down_sync(0xffffffffu, b, d);
                }
                if ((t & 31) == 0) { s_d2[t >> 5] = a; s_d2[4 + (t >> 5)] = b; }
            }
            __syncthreads();
            if (t == 0) {
                double A  = (s_d2[0] + s_d2[1]) + (s_d2[2] + s_d2[3]);
                double Bs = (s_d2[4] + s_d2[5]) + (s_d2[6] + s_d2[7]);
                s_flag = (A / (Bs + 1e-8) < 0.05) ? 1 : 0;
            }
            tag++;
            __syncthreads();
            if (s_flag) break;
            float* tmp = hc; hc = ho; ho = tmp;
        }

        // emit IMF, update residual
        float ar = 0.f, ar2 = 0.f;
#pragma unroll
        for (int q = 0; q < 2; ++q) {
            float4 hv = ((const float4*)(hc + PH(lo)))[q];
            float4 rr = *(const float4*)(resr + lo + 4 * q);
            float4 nr;
            nr.x = rr.x - hv.x; nr.y = rr.y - hv.y;
            nr.z = rr.z - hv.z; nr.w = rr.w - hv.w;
            *(float4*)(outim + lo + 4 * q) = hv;
            *(float4*)(resr + lo + 4 * q)  = nr;
            ((float4*)(ho + PH(lo)))[q]    = nr;
            ar  += nr.x + nr.y + nr.z + nr.w;
            ar2 += nr.x * nr.x + nr.y * nr.y + nr.z * nr.z + nr.w * nr.w;
        }
        __syncthreads();
        if (sub == 1 && t == 0) s_mb[9] = ho[PH(0)];   // residual seam value
        CLUSTER_SYNC();

        float ad = 0.f, ad2 = 0.f;
        {
            float c8[CHUNK];
#pragma unroll
            for (int q = 0; q < 2; ++q)
                *(float4*)&c8[4 * q] = ((const float4*)(ho + PH(lo)))[q];
            float nb;
            if (t < NT - 1) nb = ho[PH(lo + CHUNK)];
            else            nb = (sub == 0) ? dsmem_ld(&s_mb[9], 1u) : 0.f;
#pragma unroll
            for (int j = 0; j < CHUNK; ++j) {
                float nx = (j < CHUNK - 1) ? c8[j + 1] : nb;
                if (sub * HALF + lo + j < L - 1) {
                    float d = nx - c8[j];
                    ad  += d;
                    ad2 += d * d;
                }
            }
        }
        double Sd = (double)ad, Sd2 = (double)ad2;
        double Sr = (double)ar, Sr2 = (double)ar2;
        block_sum4_to0(Sd, Sd2, Sr, Sr2, s_d);
        if (t == 0) {
            double* p = &g_part[tag & 1][cta][0];
            p[0] = Sd; p[1] = Sd2; p[2] = Sr; p[3] = Sr2;
            __threadfence();
            ((volatile unsigned*)g_seq)[cta] = tag;
        }
        if (t < NCTA) {
            volatile unsigned* sq = &g_seq[t];
            while (*sq < tag) {}
        }
        __threadfence();
        if (t < NCTA) {
            volatile double* p = &g_part[tag & 1][t][0];
            double a = p[0], b = p[1], c = p[2], e = p[3];
#pragma unroll
            for (int d = 16; d; d >>= 1) {
                a += __shfl_down_sync(0xffffffffu, a, d);
                b += __shfl_down_sync(0xffffffffu, b, d);
                c += __shfl_down_sync(0xffffffffu, c, d);
                e += __shfl_down_sync(0xffffffffu, e, d);
            }
            if ((t & 31) == 0) {
                int w = t >> 5;
                s_d2[4 * w + 0] = a; s_d2[4 * w + 1] = b;
                s_d2[4 * w + 2] = c; s_d2[4 * w + 3] = e;
            }
        }
        __syncthreads();
        if (t == 0) {
            double a = (s_d2[0] + s_d2[4]) + (s_d2[8] + s_d2[12]);
            double b = (s_d2[1] + s_d2[5]) + (s_d2[9] + s_d2[13]);
            double c = (s_d2[2] + s_d2[6]) + (s_d2[10] + s_d2[14]);
            double e = (s_d2[3] + s_d2[7]) + (s_d2[11] + s_d2[15]);
            double ndv = (double)BROWS * (double)(L - 1);
            double nrv = (double)BROWS * (double)L;
            double vard = (b - a * a / ndv) / (ndv - 1.0);
            double varr = (e - c * c / nrv) / (nrv - 1.0);
            s_flag = (vard < 0.05 * varr) ? 1 : 0;
        }
        tag++;
        __syncthreads();
        if (s_flag) outer_done = true;
    }

    float* outres = out + ((size_t)NIMF * BROWS + row) * L + sub * HALF;
#pragma unroll
    for (int q = 0; q < 2; ++q)
        *(float4*)(outres + lo + 4 * q) = *(const float4*)(resr + lo + 4 * q);

    // end-of-launch rendezvous + reset for graph replays
    __syncthreads();
    if (t == 0) {
        __threadfence();
        atomicAdd(&g_count, 1u);
    }
    if (cta == 0) {
        if (t == 0) {
            volatile unsigned* vc = &g_count;
            while (*vc < (unsigned)NCTA) {}
            __threadfence();
        }
        __syncthreads();
        if (t < NCTA) ((volatile unsigned*)g_seq)[t] = 0u;
        if (t == 0) g_count = 0u;
    }
    CLUSTER_SYNC();   // no CTA exits while peer may still DSMEM-read it
}

extern "C" void kernel_launch(void* const* d_in, const int* in_sizes, int n_in,
                              void* d_out, int out_size) {
    (void)in_sizes; (void)n_in; (void)out_size;
    const size_t shmem = (size_t)(2 * LPH) * sizeof(float);
    cudaFuncSetAttribute(emd_kernel, cudaFuncAttributeMaxDynamicSharedMemorySize, (int)shmem);
    emd_kernel<<<NCTA, NT, shmem>>>((const float*)d_in[0], (float*)d_out);
}

// round 9
// speedup vs baseline: 1.3782x; 1.1152x over previous
#include <cuda_runtime.h>
#include <cstdint>

#define BROWS 64
#define L 16384
#define HALF 8192
#define NCTA 128
#define NT 1024
#define NW 32
#define CHUNK 8
#define NIMF 6
#define MAXIT 12
#define LPH (HALF + (HALF >> 1))
#define PH(i) ((i) + (((i) >> 3) << 2))

#define T_RUN (5 * NW + 0)
#define T_CM  (5 * NW + 1)
#define T_CNT (5 * NW + 2)
#define T_MAX (5 * NW + 3)
#define T_MIN (5 * NW + 4)

__device__ float    g_res[BROWS * L];
__device__ double   g_part[2][NCTA][4];
__device__ unsigned g_seq[NCTA];
__device__ unsigned g_count = 0;

__device__ __forceinline__ float negInf() { return __int_as_float(0xff800000); }
__device__ __forceinline__ float posInf() { return __int_as_float(0x7f800000); }

#define CLUSTER_SYNC() do { \
    asm volatile("barrier.cluster.arrive.aligned;" ::: "memory"); \
    asm volatile("barrier.cluster.wait.aligned;" ::: "memory"); \
} while (0)

__device__ __forceinline__ void fence_cluster() {
    asm volatile("fence.acq_rel.cluster;" ::: "memory");
}
__device__ __forceinline__ void dsmem_stf(float* p, unsigned rank, float v) {
    uint32_t a = (uint32_t)__cvta_generic_to_shared(p), r;
    asm volatile("mapa.shared::cluster.u32 %0, %1, %2;" : "=r"(r) : "r"(a), "r"(rank));
    asm volatile("st.shared::cluster.f32 [%0], %1;" :: "r"(r), "f"(v) : "memory");
}
__device__ __forceinline__ void dsmem_stu(unsigned* p, unsigned rank, unsigned v) {
    uint32_t a = (uint32_t)__cvta_generic_to_shared(p), r;
    asm volatile("mapa.shared::cluster.u32 %0, %1, %2;" : "=r"(r) : "r"(a), "r"(rank));
    asm volatile("st.shared::cluster.u32 [%0], %1;" :: "r"(r), "r"(v) : "memory");
}
__device__ __forceinline__ unsigned lds_vol(const unsigned* p) {
    unsigned v;
    asm volatile("ld.volatile.shared.u32 %0, [%1];" : "=r"(v)
                 : "r"((uint32_t)__cvta_generic_to_shared(p)) : "memory");
    return v;
}
// push one float + release tag into the peer's rx channel
__device__ __forceinline__ void halo_push(float* rx, unsigned* rxf, unsigned peer,
                                          unsigned tag, float v) {
    dsmem_stf(&rx[tag & 1], peer, v);
    fence_cluster();
    dsmem_stu(rxf, peer, tag);
}
__device__ __forceinline__ float halo_wait(float* rx, unsigned* rxf, unsigned tag) {
    while (lds_vol(rxf) < tag) {}
    fence_cluster();
    return rx[tag & 1];
}

// fused collectives + CTA totals (totals left in ubuf[T_*])
__device__ __forceinline__ void fused_coll(unsigned vmin, unsigned vmax, unsigned vsum,
                                           float cmx, float cmn, unsigned* ubuf,
                                           unsigned& offn, unsigned& offl) {
    const int lane = threadIdx.x & 31, wid = threadIdx.x >> 5;
    unsigned imin = vmin, imax = vmax, s = vsum;
    float fx = cmx, fn = cmn;
#pragma unroll
    for (int d = 1; d < 32; d <<= 1) {
        unsigned a = __shfl_down_sync(0xffffffffu, imin, d);
        if (lane + d < 32) imin = __vminu2(imin, a);
        unsigned b = __shfl_up_sync(0xffffffffu, imax, d);
        if (lane >= d) imax = __vmaxs2(imax, b);
        s += __shfl_xor_sync(0xffffffffu, s, d);
        fx = fmaxf(fx, __shfl_xor_sync(0xffffffffu, fx, d));
        fn = fminf(fn, __shfl_xor_sync(0xffffffffu, fn, d));
    }
    if (lane == 0) {
        ubuf[wid] = imin; ubuf[2 * NW + wid] = s;
        ubuf[3 * NW + wid] = __float_as_uint(fx);
        ubuf[4 * NW + wid] = __float_as_uint(fn);
    }
    if (lane == 31) ubuf[NW + wid] = imax;
    __syncthreads();
    if (wid == 0) {
        unsigned wm = ubuf[lane], wx = ubuf[NW + lane], ws = ubuf[2 * NW + lane];
        float wfx = __uint_as_float(ubuf[3 * NW + lane]);
        float wfn = __uint_as_float(ubuf[4 * NW + lane]);
#pragma unroll
        for (int d = 1; d < 32; d <<= 1) {
            unsigned a = __shfl_down_sync(0xffffffffu, wm, d);
            if (lane + d < 32) wm = __vminu2(wm, a);
            unsigned b = __shfl_up_sync(0xffffffffu, wx, d);
            if (lane >= d) wx = __vmaxs2(wx, b);
            ws += __shfl_xor_sync(0xffffffffu, ws, d);
            wfx = fmaxf(wfx, __shfl_xor_sync(0xffffffffu, wfx, d));
            wfn = fminf(wfn, __shfl_xor_sync(0xffffffffu, wfn, d));
        }
        ubuf[lane] = wm; ubuf[NW + lane] = wx;
        if (lane == 0) {
            ubuf[T_RUN] = wm; ubuf[T_CNT] = ws;
            ubuf[T_MAX] = __float_as_uint(wfx);
            ubuf[T_MIN] = __float_as_uint(wfn);
        }
        if (lane == 31) ubuf[T_CM] = wx;
    }
    __syncthreads();
    unsigned woffn = (wid < NW - 1) ? ubuf[wid + 1] : 0x40004000u;
    unsigned lexn  = __shfl_down_sync(0xffffffffu, imin, 1);
    offn = (lane < 31) ? __vminu2(woffn, lexn) : woffn;
    unsigned woffl = (wid > 0) ? ubuf[NW + wid - 1] : 0xffffffffu;
    unsigned lexl  = __shfl_up_sync(0xffffffffu, imax, 1);
    offl = (lane > 0) ? __vmaxs2(woffl, lexl) : woffl;
}

__device__ __forceinline__ float pmax_f_excl(float v, float* wbuf) {
    const int lane = threadIdx.x & 31, wid = threadIdx.x >> 5;
    float incl = v;
#pragma unroll
    for (int d = 1; d < 32; d <<= 1) {
        float u = __shfl_up_sync(0xffffffffu, incl, d);
        if (lane >= d) incl = fmaxf(incl, u);
    }
    if (lane == 31) wbuf[wid] = incl;
    __syncthreads();
    if (wid == 0) {
        float w = wbuf[lane];
#pragma unroll
        for (int d = 1; d < 32; d <<= 1) {
            float u = __shfl_up_sync(0xffffffffu, w, d);
            if (lane >= d) w = fmaxf(w, u);
        }
        wbuf[lane] = w;
    }
    __syncthreads();
    float woff = (wid > 0) ? wbuf[wid - 1] : negInf();
    float lex  = __shfl_up_sync(0xffffffffu, incl, 1);
    float ex   = (lane > 0) ? fmaxf(woff, lex) : woff;
    __syncthreads();
    return ex;
}

__device__ __forceinline__ float pmin_f_excl(float v, float* wbuf) {
    const int lane = threadIdx.x & 31, wid = threadIdx.x >> 5;
    float incl = v;
#pragma unroll
    for (int d = 1; d < 32; d <<= 1) {
        float u = __shfl_up_sync(0xffffffffu, incl, d);
        if (lane >= d) incl = fminf(incl, u);
    }
    if (lane == 31) wbuf[wid] = incl;
    __syncthreads();
    if (wid == 0) {
        float w = wbuf[lane];
#pragma unroll
        for (int d = 1; d < 32; d <<= 1) {
            float u = __shfl_up_sync(0xffffffffu, w, d);
            if (lane >= d) w = fminf(w, u);
        }
        wbuf[lane] = w;
    }
    __syncthreads();
    float woff = (wid > 0) ? wbuf[wid - 1] : posInf();
    float lex  = __shfl_up_sync(0xffffffffu, incl, 1);
    float ex   = (lane > 0) ? fminf(woff, lex) : woff;
    __syncthreads();
    return ex;
}

__device__ __forceinline__ void block_sum2_to0(double& a, double& b, double* wbuf) {
#pragma unroll
    for (int d = 16; d; d >>= 1) {
        a += __shfl_down_sync(0xffffffffu, a, d);
        b += __shfl_down_sync(0xffffffffu, b, d);
    }
    const int lane = threadIdx.x & 31, wid = threadIdx.x >> 5;
    if (lane == 0) { wbuf[wid] = a; wbuf[NW + wid] = b; }
    __syncthreads();
    if (wid == 0) {
        double wa = wbuf[lane], wb = wbuf[NW + lane];
#pragma unroll
        for (int d = 16; d; d >>= 1) {
            wa += __shfl_down_sync(0xffffffffu, wa, d);
            wb += __shfl_down_sync(0xffffffffu, wb, d);
        }
        a = wa; b = wb;
    }
}

__device__ __forceinline__ void block_sum4_to0(double& a, double& b, double& c, double& e,
                                               double* wbuf) {
#pragma unroll
    for (int d = 16; d; d >>= 1) {
        a += __shfl_down_sync(0xffffffffu, a, d);
        b += __shfl_down_sync(0xffffffffu, b, d);
        c += __shfl_down_sync(0xffffffffu, c, d);
        e += __shfl_down_sync(0xffffffffu, e, d);
    }
    const int lane = threadIdx.x & 31, wid = threadIdx.x >> 5;
    if (lane == 0) {
        wbuf[wid] = a; wbuf[NW + wid] = b;
        wbuf[2 * NW + wid] = c; wbuf[3 * NW + wid] = e;
    }
    __syncthreads();
    if (wid == 0) {
        double wa = wbuf[lane], wb = wbuf[NW + lane];
        double wc = wbuf[2 * NW + lane], we = wbuf[3 * NW + lane];
#pragma unroll
        for (int d = 16; d; d >>= 1) {
            wa += __shfl_down_sync(0xffffffffu, wa, d);
            wb += __shfl_down_sync(0xffffffffu, wb, d);
            wc += __shfl_down_sync(0xffffffffu, wc, d);
            we += __shfl_down_sync(0xffffffffu, we, d);
        }
        a = wa; b = wb; c = wc; e = we;
    }
}

// per-thread sift front state
struct FS {
    unsigned mU, mL;
    int off_nu, off_nl;
    int runl_u, runl_l;
    float vl_u, vl_l;
    float fbU, fbL;
    float pFPU, pFPL;
    int few;
};

// walk A + collectives + cluster exchange (R8-identical values)
__device__ FS front(const float* __restrict__ hc, int sub,
                    unsigned* ubuf, float* fbuf,
                    float* rxh, unsigned* rxh_f,
                    float (*rxm)[9], unsigned* rxm_f,
                    unsigned hp, unsigned mp)
{
    const int t = threadIdx.x;
    const int lo = t * CHUNK;
    const int loG = sub * HALF;
    const int gbase = loG + lo;
    const unsigned peer = (unsigned)(sub ^ 1);

    float h8[CHUNK];
    const float* cbase = hc + PH(lo);
    *(float4*)&h8[0] = ((const float4*)cbase)[0];
    *(float4*)&h8[4] = ((const float4*)cbase)[1];

    float prev, nextB;
    if (t > 0)           prev = hc[PH(lo - 1)];
    else if (sub == 1)   prev = halo_wait(rxh, rxh_f, hp);
    else                 prev = 0.f;
    if (t < NT - 1)      nextB = hc[PH(lo + CHUNK)];
    else if (sub == 0)   nextB = halo_wait(rxh, rxh_f, hp);
    else                 nextB = 0.f;

    unsigned mU = 0, mL = 0;
    float cmx = negInf(), cmn = posInf();
#pragma unroll
    for (int j = 0; j < CHUNK; ++j) {
        float cur = h8[j];
        float nxt = (j < CHUNK - 1) ? h8[j + 1] : nextB;
        mU |= (unsigned)((prev < cur) & (cur > nxt)) << j;
        mL |= (unsigned)((prev > cur) & (cur < nxt)) << j;
        cmx = fmaxf(cmx, cur); cmn = fminf(cmn, cur);
        prev = cur;
    }
    if (sub == 0 && t == 0)      { mU &= ~1u;   mL &= ~1u;   }
    if (sub == 1 && t == NT - 1) { mU &= 0x7fu; mL &= 0x7fu; }

    int run_u = mU ? gbase + (__ffs(mU) - 1) : L;
    int run_l = mL ? gbase + (__ffs(mL) - 1) : L;
    int cm_u  = mU ? gbase + (31 - __clz((int)mU)) : -1;
    int cm_l  = mL ? gbase + (31 - __clz((int)mL)) : -1;
    unsigned cnt = (unsigned)__popc(mU) | ((unsigned)__popc(mL) << 16);

    unsigned offn, offl;
    fused_coll((unsigned)run_u | ((unsigned)run_l << 16),
               ((unsigned)cm_u & 0xffffu) | (((unsigned)cm_l & 0xffffu) << 16),
               cnt, cmx, cmn, ubuf, offn, offl);

    if (t == 0) {
        unsigned tr = ubuf[T_RUN], tc = ubuf[T_CM];
        int fu = (int)(tr & 0xffffu), fl2 = (int)(tr >> 16);
        int lu = (int)(short)(tc & 0xffffu), ll = (int)(short)(tc >> 16);
        float vals[9];
        vals[0] = __uint_as_float(tr);
        vals[1] = __uint_as_float(tc);
        vals[2] = __uint_as_float(ubuf[T_CNT]);
        vals[3] = __uint_as_float(ubuf[T_MAX]);
        vals[4] = __uint_as_float(ubuf[T_MIN]);
        vals[5] = (fu  < L)  ? hc[PH(fu  - loG)] : 0.f;
        vals[6] = (fl2 < L)  ? hc[PH(fl2 - loG)] : 0.f;
        vals[7] = (lu  >= 0) ? hc[PH(lu  - loG)] : 0.f;
        vals[8] = (ll  >= 0) ? hc[PH(ll  - loG)] : 0.f;
#pragma unroll
        for (int k = 0; k < 9; ++k) dsmem_stf(&rxm[mp & 1][k], peer, vals[k]);
        fence_cluster();
        dsmem_stu(rxm_f, peer, mp);
        while (lds_vol(rxm_f) < mp) {}
        fence_cluster();
    }
    __syncthreads();
    const float* pv = rxm[mp & 1];
    float p0 = pv[0], p1 = pv[1], p2 = pv[2], p3 = pv[3], p4 = pv[4];
    float pFPU = pv[5], pFPL = pv[6], pLPU = pv[7], pLPL = pv[8];

    unsigned totc = ubuf[T_CNT] + __float_as_uint(p2);
    if (sub == 0) offn = __vminu2(offn, __float_as_uint(p0));
    else          offl = __vmaxs2(offl, __float_as_uint(p1));

    FS st;
    st.mU = mU; st.mL = mL;
    st.off_nu = (int)(offn & 0xffffu);
    st.off_nl = (int)(offn >> 16);
    st.runl_u = (int)(short)(offl & 0xffffu);
    st.runl_l = (int)(short)(offl >> 16);
    bool few_u = (totc & 0xffffu) < 2u;
    bool few_l = (totc >> 16)     < 2u;
    st.few = (few_u ? 1 : 0) | (few_l ? 2 : 0);
    st.fbU = negInf(); st.fbL = posInf();
    if (few_u) {
        float ex = pmax_f_excl(cmx, fbuf);
        st.fbU = (sub == 1) ? fmaxf(ex, p3) : ex;
    }
    if (few_l) {
        float ex = pmin_f_excl(cmn, fbuf);
        st.fbL = (sub == 1) ? fminf(ex, p4) : ex;
    }
    st.vl_u = (st.runl_u >= loG) ? hc[PH(st.runl_u - loG)] : pLPU;
    st.vl_l = (st.runl_l >= loG) ? hc[PH(st.runl_l - loG)] : pLPL;
    st.pFPU = pFPU; st.pFPL = pFPL;
    return st;
}

// walk B (R8-identical arithmetic) + halo push of ho edges
__device__ void walkB(const float* __restrict__ hc, float* __restrict__ ho,
                      FS st, int sub,
                      float* rxh, unsigned* rxh_f, unsigned hp_out,
                      float& o_m, float& o_h2)
{
    const int t = threadIdx.x;
    const int lo = t * CHUNK;
    const int loG = sub * HALF, hiG = loG + HALF;
    const int gbase = loG + lo;
    const unsigned peer = (unsigned)(sub ^ 1);

    float h8[CHUNK];
    const float* cbase = hc + PH(lo);
    *(float4*)&h8[0] = ((const float4*)cbase)[0];
    *(float4*)&h8[4] = ((const float4*)cbase)[1];

    const bool few_u = (st.few & 1) != 0, few_l = (st.few & 2) != 0;
    int   runl_u = st.runl_u, runl_l = st.runl_l;
    float vl_u = st.vl_u, vl_l = st.vl_l;
    float fbU = st.fbU, fbL = st.fbL;
    int   cur_nu = -0x40000000, cur_nl = -0x40000000;
    float vr_u = 0.f, vr_l = 0.f;
    float acc_m = 0.f, acc_h = 0.f;
    float firstO = 0.f, lastO = 0.f;
    float* obase = ho + PH(lo);

#pragma unroll
    for (int q = 0; q < 2; ++q) {
        float4 ov;
#pragma unroll
        for (int r = 0; r < 4; ++r) {
            const int j = 4 * q + r;
            const int gi = gbase + j;
            const float hv = h8[j];

            if ((st.mU >> j) & 1u) { runl_u = gi; vl_u = hv; }
            unsigned remU = st.mU >> j;
            int nu = remU ? gi + (__ffs(remU) - 1) : st.off_nu;
            if (nu != cur_nu) { cur_nu = nu; vr_u = (nu < hiG) ? hc[PH(nu - loG)] : st.pFPU; }
            float eu;
            {
                int den = nu - runl_u;
                eu = (den > 0) ? vl_u + ((float)(gi - runl_u) / (float)den) * (vr_u - vl_u)
                               : vl_u;
                if (runl_u < 0) eu = vr_u;
                if (nu >= L)    eu = vl_u;
            }
            if (few_u) { fbU = fmaxf(fbU, hv); eu = fbU; }

            if ((st.mL >> j) & 1u) { runl_l = gi; vl_l = hv; }
            unsigned remL = st.mL >> j;
            int nl = remL ? gi + (__ffs(remL) - 1) : st.off_nl;
            if (nl != cur_nl) { cur_nl = nl; vr_l = (nl < hiG) ? hc[PH(nl - loG)] : st.pFPL; }
            float el;
            {
                int den = nl - runl_l;
                el = (den > 0) ? vl_l + ((float)(gi - runl_l) / (float)den) * (vr_l - vl_l)
                               : vl_l;
                if (runl_l < 0) el = vr_l;
                if (nl >= L)    el = vl_l;
            }
            if (few_l) { fbL = fminf(fbL, hv); el = fbL; }

            float mean = 0.5f * (eu + el);
            float o = hv - mean;
            if (j == 0) firstO = o;
            lastO = o;
            acc_m += mean * mean;
            acc_h += hv * hv;
            switch (r) {
                case 0: ov.x = o; break;
                case 1: ov.y = o; break;
                case 2: ov.z = o; break;
                default: ov.w = o; break;
            }
        }
        ((float4*)obase)[q] = ov;
    }
    o_m = acc_m; o_h2 = acc_h;

    if (sub == 0 && t == NT - 1) halo_push(rxh, rxh_f, peer, hp_out, lastO);
    if (sub == 1 && t == 0)      halo_push(rxh, rxh_f, peer, hp_out, firstO);
}

__global__ void __launch_bounds__(NT, 1) __cluster_dims__(2, 1, 1)
emd_kernel(const float* __restrict__ x, float* __restrict__ out)
{
    extern __shared__ unsigned char dynsm[];
    float* bufA = (float*)dynsm;
    float* bufB = bufA + LPH;

    __shared__ unsigned s_u[5 * NW + 5];
    __shared__ float    s_f[NW + 1];
    __shared__ double   s_d[4 * NW];
    __shared__ double   s_d2[16];
    __shared__ int      s_flag;
    __shared__ float    s_rxh[2];
    __shared__ float    s_rxm[2][9];
    __shared__ unsigned s_rxh_f, s_rxm_f;

    const int t   = threadIdx.x;
    const int lo  = t * CHUNK;
    const int cta = blockIdx.x;
    const int row = cta >> 1;
    unsigned rk;
    asm("mov.u32 %0, %%cluster_ctarank;" : "=r"(rk));
    const int sub = (int)rk;
    const unsigned peer = (unsigned)(sub ^ 1);

    if (t == 0) { s_rxh_f = 0u; s_rxm_f = 0u; }
    __syncthreads();
    CLUSTER_SYNC();   // flags initialized in both CTAs before any remote push

    const float* xr   = x + (size_t)row * L + sub * HALF;
    float*       resr = g_res + (size_t)row * L + sub * HALF;
#pragma unroll
    for (int q = 0; q < 2; ++q)
        *(float4*)(resr + lo + 4 * q) = *(const float4*)(xr + lo + 4 * q);

    unsigned tag = 1, hp = 0, mp = 0;
    bool outer_done = false;

    for (int im = 0; im < NIMF; ++im) {
        float* outim = out + ((size_t)im * BROWS + row) * L + sub * HALF;
        if (outer_done) {
            float4 z = make_float4(0.f, 0.f, 0.f, 0.f);
#pragma unroll
            for (int q = 0; q < 2; ++q) *(float4*)(outim + lo + 4 * q) = z;
            continue;  // globally uniform
        }

        float* hc = bufA;
        float* ho = bufB;
#pragma unroll
        for (int q = 0; q < 2; ++q)
            ((float4*)(hc + PH(lo)))[q] = *(const float4*)(resr + lo + 4 * q);
        __syncthreads();

        hp++;
        if (sub == 0 && t == NT - 1) halo_push(s_rxh, &s_rxh_f, peer, hp, hc[PH(HALF - 1)]);
        if (sub == 1 && t == 0)      halo_push(s_rxh, &s_rxh_f, peer, hp, hc[PH(0)]);
        mp++;
        FS st = front(hc, sub, s_u, s_f, s_rxh, &s_rxh_f, s_rxm, &s_rxm_f, hp, mp);

        for (int it = 0; it < MAXIT; ++it) {
            float fm, fh2;
            hp++;
            walkB(hc, ho, st, sub, s_rxh, &s_rxh_f, hp, fm, fh2);
            double sm = (double)fm, sh2 = (double)fh2;
            block_sum2_to0(sm, sh2, s_d);           // syncthreads inside orders ho
            if (t == 0) {
                double* p = &g_part[tag & 1][cta][0];
                p[0] = sm; p[1] = sh2;
                __threadfence();
                ((volatile unsigned*)g_seq)[cta] = tag;
            }
            // speculative front for next iteration, hidden under the grid sync
            FS st2;
            const bool spec = (it + 1 < MAXIT);
            if (spec) {
                mp++;
                st2 = front(ho, sub, s_u, s_f, s_rxh, &s_rxh_f, s_rxm, &s_rxm_f, hp, mp);
            }
            if (t < NCTA) {
                volatile unsigned* sq = &g_seq[t];
                while (*sq < tag) {}
            }
            __threadfence();
            if (t < NCTA) {
                volatile double* p = &g_part[tag & 1][t][0];
                double a = p[0], b = p[1];
#pragma unroll
                for (int d = 16; d; d >>= 1) {
                    a += __shfl_down_sync(0xffffffffu, a, d);
                    b += __shfl_down_sync(0xffffffffu, b, d);
                }
                if ((t & 31) == 0) { s_d2[t >> 5] = a; s_d2[4 + (t >> 5)] = b; }
            }
            __syncthreads();
            if (t == 0) {
                double A  = (s_d2[0] + s_d2[1]) + (s_d2[2] + s_d2[3]);
                double Bs = (s_d2[4] + s_d2[5]) + (s_d2[6] + s_d2[7]);
                s_flag = (A / (Bs + 1e-8) < 0.05) ? 1 : 0;
            }
            tag++;
            __syncthreads();
            if (s_flag) break;
            float* tmp = hc; hc = ho; ho = tmp;
            st = st2;
        }

        // emit IMF, update residual
        float ar = 0.f, ar2 = 0.f;
#pragma unroll
        for (int q = 0; q < 2; ++q) {
            float4 hv = ((const float4*)(hc + PH(lo)))[q];
            float4 rr = *(const float4*)(resr + lo + 4 * q);
            float4 nr;
            nr.x = rr.x - hv.x; nr.y = rr.y - hv.y;
            nr.z = rr.z - hv.z; nr.w = rr.w - hv.w;
            *(float4*)(outim + lo + 4 * q) = hv;
            *(float4*)(resr + lo + 4 * q)  = nr;
            ((float4*)(ho + PH(lo)))[q]    = nr;
            ar  += nr.x + nr.y + nr.z + nr.w;
            ar2 += nr.x * nr.x + nr.y * nr.y + nr.z * nr.z + nr.w * nr.w;
        }
        __syncthreads();
        hp++;
        if (sub == 0 && t == NT - 1) halo_push(s_rxh, &s_rxh_f, peer, hp, ho[PH(HALF - 1)]);
        if (sub == 1 && t == 0)      halo_push(s_rxh, &s_rxh_f, peer, hp, ho[PH(0)]);

        float ad = 0.f, ad2 = 0.f;
        {
            float c8[CHUNK];
#pragma unroll
            for (int q = 0; q < 2; ++q)
                *(float4*)&c8[4 * q] = ((const float4*)(ho + PH(lo)))[q];
            float nb;
            if (t < NT - 1)    nb = ho[PH(lo + CHUNK)];
            else if (sub == 0) nb = halo_wait(s_rxh, &s_rxh_f, hp);
            else               nb = 0.f;
#pragma unroll
            for (int j = 0; j < CHUNK; ++j) {
                float nx = (j < CHUNK - 1) ? c8[j + 1] : nb;
                if (sub * HALF + lo + j < L - 1) {
                    float d = nx - c8[j];
                    ad  += d;
                    ad2 += d * d;
                }
            }
        }
        double Sd = (double)ad, Sd2 = (double)ad2;
        double Sr = (double)ar, Sr2 = (double)ar2;
        block_sum4_to0(Sd, Sd2, Sr, Sr2, s_d);
        if (t == 0) {
            double* p = &g_part[tag & 1][cta][0];
            p[0] = Sd; p[1] = Sd2; p[2] = Sr; p[3] = Sr2;
            __threadfence();
            ((volatile unsigned*)g_seq)[cta] = tag;
        }
        if (t < NCTA) {
            volatile unsigned* sq = &g_seq[t];
            while (*sq < tag) {}
        }
        __threadfence();
        if (t < NCTA) {
            volatile double* p = &g_part[tag & 1][t][0];
            double a = p[0], b = p[1], c = p[2], e = p[3];
#pragma unroll
            for (int d = 16; d; d >>= 1) {
                a += __shfl_down_sync(0xffffffffu, a, d);
                b += __shfl_down_sync(0xffffffffu, b, d);
                c += __shfl_down_sync(0xffffffffu, c, d);
                e += __shfl_down_sync(0xffffffffu, e, d);
            }
            if ((t & 31) == 0) {
                int w = t >> 5;
                s_d2[4 * w + 0] = a; s_d2[4 * w + 1] = b;
                s_d2[4 * w + 2] = c; s_d2[4 * w + 3] = e;
            }
        }
        __syncthreads();
        if (t == 0) {
            double a = (s_d2[0] + s_d2[4]) + (s_d2[8] + s_d2[12]);
            double b = (s_d2[1] + s_d2[5]) + (s_d2[9] + s_d2[13]);
            double c = (s_d2[2] + s_d2[6]) + (s_d2[10] + s_d2[14]);
            double e = (s_d2[3] + s_d2[7]) + (s_d2[11] + s_d2[15]);
            double ndv = (double)BROWS * (double)(L - 1);
            double nrv = (double)BROWS * (double)L;
            double vard = (b - a * a / ndv) / (ndv - 1.0);
            double varr = (e - c * c / nrv) / (nrv - 1.0);
            s_flag = (vard < 0.05 * varr) ? 1 : 0;
        }
        tag++;
        __syncthreads();
        if (s_flag) outer_done = true;
    }

    float* outres = out + ((size_t)NIMF * BROWS + row) * L + sub * HALF;
#pragma unroll
    for (int q = 0; q < 2; ++q)
        *(float4*)(outres + lo + 4 * q) = *(const float4*)(resr + lo + 4 * q);

    // end-of-launch rendezvous + reset for graph replays
    __syncthreads();
    if (t == 0) {
        __threadfence();
        atomicAdd(&g_count, 1u);
    }
    if (cta == 0) {
        if (t == 0) {
            volatile unsigned* vc = &g_count;
            while (*vc < (unsigned)NCTA) {}
            __threadfence();
        }
        __syncthreads();
        if (t < NCTA) ((volatile unsigned*)g_seq)[t] = 0u;
        if (t == 0) g_count = 0u;
    }
    CLUSTER_SYNC();   // no CTA exits while peer may still remote-write its smem
}

extern "C" void kernel_launch(void* const* d_in, const int* in_sizes, int n_in,
                              void* d_out, int out_size) {
    (void)in_sizes; (void)n_in; (void)out_size;
    const size_t shmem = (size_t)(2 * LPH) * sizeof(float);
    cudaFuncSetAttribute(emd_kernel, cudaFuncAttributeMaxDynamicSharedMemorySize, (int)shmem);
    emd_kernel<<<NCTA, NT, shmem>>>((const float*)d_in[0], (float*)d_out);
}